// round 2
// baseline (speedup 1.0000x reference)
#include <cuda_runtime.h>
#include <math.h>

// Problem constants
#define Bz 32
#define Ss 96
#define Tt 96
#define Ee 200
#define Hh 512
#define Vv 30000
#define G4 2048   // 4*H

// ---------------- scratch (device globals; no runtime allocation) ----------
__device__ float d_gxf[(size_t)Ss * G4 * Bz];        // [s][4H][b] precomputed x-gates fwd
__device__ float d_gxb[(size_t)Ss * G4 * Bz];        // [s][4H][b] bwd (time-reversed)
__device__ float d_gxd[(size_t)(Tt - 1) * G4 * Bz];  // [t][4H][b] decoder
__device__ float d_hping[2 * 2 * Hh * Bz];           // encoder h ping-pong [dir][buf][k][b]
__device__ float d_hdping[2 * Hh * Bz];              // decoder h ping-pong [buf][k][b]
__device__ float d_hfin[2 * Hh * Bz];                // final enc h [dir][k][b]
__device__ float d_cfin[2 * Hh * Bz];                // final enc c [dir][k][b]
__device__ float d_c0[Hh * Bz];                      // decoder c0 [k][b]
__device__ float d_hs[(size_t)(Tt - 1) * Bz * Hh];   // decoder hidden states [t*32+b][k]
__device__ int d_idxf[Ss * Bz];
__device__ int d_idxb[Ss * Bz];
__device__ int d_idxd[(Tt - 1) * Bz];
__device__ unsigned long long d_bar_enc;
__device__ unsigned long long d_bar_dec;

// ---------------- grid barrier (monotone counter, all CTAs resident) -------
__device__ __forceinline__ void grid_sync(unsigned long long* ctr, unsigned int nb) {
    __syncthreads();
    if (threadIdx.x == 0) {
        __threadfence();
        unsigned long long arrival = atomicAdd(ctr, 1ULL) + 1ULL;
        unsigned long long target = ((arrival + nb - 1ULL) / nb) * (unsigned long long)nb;
        while (*((volatile unsigned long long*)ctr) < target) { }
        __threadfence();
    }
    __syncthreads();
}

// ---------------- index build -------------------------------------------------
__global__ void k_idx(const int* __restrict__ Problem, const int* __restrict__ LF) {
    int m = blockIdx.x * blockDim.x + threadIdx.x;
    if (m < Ss * Bz) {
        int s = m >> 5, b = m & 31;
        d_idxf[m] = Problem[b * Ss + s];
        d_idxb[m] = Problem[b * Ss + (Ss - 1 - s)];
    }
    if (m < (Tt - 1) * Bz) {
        int t = m >> 5, b = m & 31;
        d_idxd[m] = LF[b * Tt + t];
    }
}

// ---------------- zero the t=0 output slice ----------------------------------
__global__ void k_zero_t0(float* __restrict__ out) {
    long i = (long)blockIdx.x * blockDim.x + threadIdx.x;
    if (i < (long)Bz * Vv) {
        long b = i / Vv;
        long n = i - b * Vv;
        out[b * (long)Tt * Vv + n] = 0.f;
    }
}

// ---------------- generic tiled SGEMM: C = gather(A) @ W^T + bias ------------
// A rows optionally gathered through an index array. W is [N][K] row-major.
// which_idx: 0/1/2 -> gather via d_idx{f,b,d};  3 -> A is the internal d_hs
//            symbol (selected IN-KERNEL; host passes nullptr), no gather.
// mode 0: out[m*N+n]   (plain row-major)
// mode 1: out[(m&31)][ (m>>5)+1 ][n] into (B, T, V) logits tensor
// mode 2: out[(m>>5)*N*32 + n*32 + (m&31)]  (batch-minor for scan kernels)
__global__ void __launch_bounds__(256) k_sgemm(
    const float* __restrict__ A, const float* __restrict__ W,
    const float* __restrict__ bias, float* __restrict__ out_ext,
    int M, int N, int K, int which_out, int which_idx, int mode)
{
    __shared__ float As[8][64];
    __shared__ float Bs[8][64];

    float* out = (which_out == 0) ? d_gxf : (which_out == 1) ? d_gxb
               : (which_out == 2) ? d_gxd : out_ext;
    const int* ridx = (which_idx == 0) ? d_idxf : (which_idx == 1) ? d_idxb
                    : (which_idx == 2) ? d_idxd : (const int*)0;
    // Critical: device-side selection of the hidden-state buffer. Host code
    // must NOT pass &d_hs (host shadow address) — that was the R1 bug.
    const float* Aeff = (which_idx == 3) ? (const float*)d_hs : A;

    int tid = threadIdx.x;
    int m0 = blockIdx.y * 64, n0 = blockIdx.x * 64;
    int tx = tid & 15, ty = tid >> 4;

    float acc[4][4];
#pragma unroll
    for (int i = 0; i < 4; i++)
#pragma unroll
        for (int j = 0; j < 4; j++) acc[i][j] = 0.f;

    for (int k0 = 0; k0 < K; k0 += 8) {
        if (tid < 128) {
            int mi = tid >> 1;
            int kq = (tid & 1) * 4;
            int m = m0 + mi;
            float4 v = make_float4(0.f, 0.f, 0.f, 0.f);
            if (m < M) {
                long row = ridx ? (long)ridx[m] : (long)m;
                v = *(const float4*)(Aeff + row * (long)K + k0 + kq);
            }
            As[kq + 0][mi] = v.x; As[kq + 1][mi] = v.y;
            As[kq + 2][mi] = v.z; As[kq + 3][mi] = v.w;
        } else {
            int t = tid - 128;
            int ni = t >> 1;
            int kq = (t & 1) * 4;
            int n = n0 + ni;
            float4 v = make_float4(0.f, 0.f, 0.f, 0.f);
            if (n < N) v = *(const float4*)(W + (long)n * K + k0 + kq);
            Bs[kq + 0][ni] = v.x; Bs[kq + 1][ni] = v.y;
            Bs[kq + 2][ni] = v.z; Bs[kq + 3][ni] = v.w;
        }
        __syncthreads();
#pragma unroll
        for (int kk = 0; kk < 8; kk++) {
            float4 a0 = *(const float4*)&As[kk][ty * 4];
            float4 b0 = *(const float4*)&Bs[kk][tx * 4];
            acc[0][0] += a0.x * b0.x; acc[0][1] += a0.x * b0.y; acc[0][2] += a0.x * b0.z; acc[0][3] += a0.x * b0.w;
            acc[1][0] += a0.y * b0.x; acc[1][1] += a0.y * b0.y; acc[1][2] += a0.y * b0.z; acc[1][3] += a0.y * b0.w;
            acc[2][0] += a0.z * b0.x; acc[2][1] += a0.z * b0.y; acc[2][2] += a0.z * b0.z; acc[2][3] += a0.z * b0.w;
            acc[3][0] += a0.w * b0.x; acc[3][1] += a0.w * b0.y; acc[3][2] += a0.w * b0.z; acc[3][3] += a0.w * b0.w;
        }
        __syncthreads();
    }

#pragma unroll
    for (int i = 0; i < 4; i++) {
        int m = m0 + ty * 4 + i;
        if (m >= M) continue;
#pragma unroll
        for (int j = 0; j < 4; j++) {
            int n = n0 + tx * 4 + j;
            if (n >= N) continue;
            float v = acc[i][j] + bias[n];
            if (mode == 0) {
                out[(size_t)m * N + n] = v;
            } else if (mode == 1) {
                out[((size_t)(m & 31) * Tt + (m >> 5) + 1) * (size_t)Vv + n] = v;
            } else {
                out[((size_t)(m >> 5) * N + n) * 32 + (m & 31)] = v;
            }
        }
    }
}

// ---------------- LSTM cell math ---------------------------------------------
__device__ __forceinline__ void lstm_cell(float ai, float af, float ag, float ao,
                                          float& c, float& h) {
    float si = 1.f / (1.f + expf(-ai));
    float sf = 1.f / (1.f + expf(-af));
    float so = 1.f / (1.f + expf(-ao));
    float tg = tanhf(ag);
    c = sf * c + si * tg;
    h = so * tanhf(c);
}

// ---------------- encoder scan: fwd + bwd in one persistent kernel -----------
// grid = 128 blocks x 256 threads. blocks [0,64) = fwd, [64,128) = bwd.
// warp w of a block owns hidden unit j; lane = batch b. c kept in register.
__global__ void __launch_bounds__(256) k_enc_scan(const float* __restrict__ Whf,
                                                  const float* __restrict__ Whb) {
    __shared__ float hsh[128 * Bz];  // 16 KB chunk of h, transposed [k][b]
    int dir = blockIdx.x >> 6;
    int w = threadIdx.x >> 5, b = threadIdx.x & 31;
    int j = ((blockIdx.x & 63) << 3) + w;

    const float* gx = dir ? d_gxb : d_gxf;
    const float* Whh = dir ? Whb : Whf;
    float* hbuf = d_hping + (size_t)dir * (2 * Hh * Bz);

    const float* w_i = Whh + ((size_t)(0 * Hh + j)) * Hh;
    const float* w_f = Whh + ((size_t)(1 * Hh + j)) * Hh;
    const float* w_g = Whh + ((size_t)(2 * Hh + j)) * Hh;
    const float* w_o = Whh + ((size_t)(3 * Hh + j)) * Hh;

    float c = 0.f, h = 0.f;

    for (int s = 0; s < Ss; s++) {
        const float* g0 = gx + (size_t)s * G4 * Bz;
        float ai = g0[(0 * Hh + j) * Bz + b];
        float af = g0[(1 * Hh + j) * Bz + b];
        float ag = g0[(2 * Hh + j) * Bz + b];
        float ao = g0[(3 * Hh + j) * Bz + b];

        if (s > 0) {
            const float* hcur = hbuf + (size_t)(s & 1) * Hh * Bz;
            for (int kc = 0; kc < Hh; kc += 128) {
                __syncthreads();
#pragma unroll
                for (int t = 0; t < 4; t++)
                    ((float4*)hsh)[threadIdx.x + t * 256] =
                        ((const float4*)(hcur + kc * Bz))[threadIdx.x + t * 256];
                __syncthreads();
#pragma unroll 8
                for (int k = 0; k < 128; k += 4) {
                    float4 wi = *(const float4*)(w_i + kc + k);
                    float4 wf = *(const float4*)(w_f + kc + k);
                    float4 wg = *(const float4*)(w_g + kc + k);
                    float4 wo = *(const float4*)(w_o + kc + k);
                    float h0 = hsh[(k + 0) * Bz + b];
                    float h1 = hsh[(k + 1) * Bz + b];
                    float h2 = hsh[(k + 2) * Bz + b];
                    float h3 = hsh[(k + 3) * Bz + b];
                    ai += wi.x * h0 + wi.y * h1 + wi.z * h2 + wi.w * h3;
                    af += wf.x * h0 + wf.y * h1 + wf.z * h2 + wf.w * h3;
                    ag += wg.x * h0 + wg.y * h1 + wg.z * h2 + wg.w * h3;
                    ao += wo.x * h0 + wo.y * h1 + wo.z * h2 + wo.w * h3;
                }
            }
        }
        lstm_cell(ai, af, ag, ao, c, h);
        hbuf[(size_t)((s + 1) & 1) * Hh * Bz + j * Bz + b] = h;
        grid_sync(&d_bar_enc, 128);
    }
    d_hfin[(size_t)dir * Hh * Bz + j * Bz + b] = h;
    d_cfin[(size_t)dir * Hh * Bz + j * Bz + b] = c;
}

// ---------------- bridge: h0 = [hf,hb]@Wh^T+bh ; c0 = [cf,cb]@Wc^T+bc --------
// h0 from HIDDEN states (d_hfin), c0 from CELL states (d_cfin), one pass.
__global__ void __launch_bounds__(256) k_h0c0(const float* __restrict__ Wh,
                                              const float* __restrict__ bh,
                                              const float* __restrict__ Wc,
                                              const float* __restrict__ bc) {
    int g = blockIdx.x * blockDim.x + threadIdx.x;  // 16384 threads
    int j = g >> 5, b = g & 31;
    const float* whr = Wh + (size_t)j * (2 * Hh);
    const float* wcr = Wc + (size_t)j * (2 * Hh);
    float ah = bh[j], ac = bc[j];
#pragma unroll 4
    for (int k = 0; k < 2 * Hh; k += 4) {
        float4 w1 = *(const float4*)(whr + k);
        float4 w2 = *(const float4*)(wcr + k);
        float hv0 = d_hfin[(k + 0) * Bz + b];
        float hv1 = d_hfin[(k + 1) * Bz + b];
        float hv2 = d_hfin[(k + 2) * Bz + b];
        float hv3 = d_hfin[(k + 3) * Bz + b];
        float cv0 = d_cfin[(k + 0) * Bz + b];
        float cv1 = d_cfin[(k + 1) * Bz + b];
        float cv2 = d_cfin[(k + 2) * Bz + b];
        float cv3 = d_cfin[(k + 3) * Bz + b];
        ah += w1.x * hv0 + w1.y * hv1 + w1.z * hv2 + w1.w * hv3;
        ac += w2.x * cv0 + w2.y * cv1 + w2.z * cv2 + w2.w * cv3;
    }
    d_hdping[j * Bz + b] = ah;   // decoder reads buf 0 at t=0
    d_c0[j * Bz + b] = ac;
}

// ---------------- decoder scan (persistent, 64 blocks) -----------------------
__global__ void __launch_bounds__(256) k_dec_scan(const float* __restrict__ Whh) {
    __shared__ float hsh[128 * Bz];
    int w = threadIdx.x >> 5, b = threadIdx.x & 31;
    int j = (blockIdx.x << 3) + w;

    const float* w_i = Whh + ((size_t)(0 * Hh + j)) * Hh;
    const float* w_f = Whh + ((size_t)(1 * Hh + j)) * Hh;
    const float* w_g = Whh + ((size_t)(2 * Hh + j)) * Hh;
    const float* w_o = Whh + ((size_t)(3 * Hh + j)) * Hh;

    float c = d_c0[j * Bz + b];
    float h = 0.f;

    for (int t = 0; t < Tt - 1; t++) {
        const float* g0 = d_gxd + (size_t)t * G4 * Bz;
        float ai = g0[(0 * Hh + j) * Bz + b];
        float af = g0[(1 * Hh + j) * Bz + b];
        float ag = g0[(2 * Hh + j) * Bz + b];
        float ao = g0[(3 * Hh + j) * Bz + b];

        const float* hcur = d_hdping + (size_t)(t & 1) * Hh * Bz;
        for (int kc = 0; kc < Hh; kc += 128) {
            __syncthreads();
#pragma unroll
            for (int q = 0; q < 4; q++)
                ((float4*)hsh)[threadIdx.x + q * 256] =
                    ((const float4*)(hcur + kc * Bz))[threadIdx.x + q * 256];
            __syncthreads();
#pragma unroll 8
            for (int k = 0; k < 128; k += 4) {
                float4 wi = *(const float4*)(w_i + kc + k);
                float4 wf = *(const float4*)(w_f + kc + k);
                float4 wg = *(const float4*)(w_g + kc + k);
                float4 wo = *(const float4*)(w_o + kc + k);
                float h0 = hsh[(k + 0) * Bz + b];
                float h1 = hsh[(k + 1) * Bz + b];
                float h2 = hsh[(k + 2) * Bz + b];
                float h3 = hsh[(k + 3) * Bz + b];
                ai += wi.x * h0 + wi.y * h1 + wi.z * h2 + wi.w * h3;
                af += wf.x * h0 + wf.y * h1 + wf.z * h2 + wf.w * h3;
                ag += wg.x * h0 + wg.y * h1 + wg.z * h2 + wg.w * h3;
                ao += wo.x * h0 + wo.y * h1 + wo.z * h2 + wo.w * h3;
            }
        }
        lstm_cell(ai, af, ag, ao, c, h);
        d_hdping[(size_t)((t + 1) & 1) * Hh * Bz + j * Bz + b] = h;
        d_hs[((size_t)t * Bz + b) * Hh + j] = h;
        grid_sync(&d_bar_dec, 64);
    }
}

// ---------------- launch -----------------------------------------------------
extern "C" void kernel_launch(void* const* d_in, const int* in_sizes, int n_in,
                              void* d_out, int out_size) {
    (void)in_sizes; (void)n_in; (void)out_size;
    const int*   Problem   = (const int*)d_in[0];
    const int*   LF        = (const int*)d_in[1];
    const float* enc_embed = (const float*)d_in[2];
    const float* dec_embed = (const float*)d_in[3];
    const float* enc_Wih_f = (const float*)d_in[4];
    const float* enc_Whh_f = (const float*)d_in[5];
    const float* enc_b_f   = (const float*)d_in[6];
    const float* enc_Wih_b = (const float*)d_in[7];
    const float* enc_Whh_b = (const float*)d_in[8];
    const float* enc_b_b   = (const float*)d_in[9];
    const float* Wh        = (const float*)d_in[10];
    const float* bh        = (const float*)d_in[11];
    const float* Wc        = (const float*)d_in[12];
    const float* bc        = (const float*)d_in[13];
    const float* dec_Wih   = (const float*)d_in[14];
    const float* dec_Whh   = (const float*)d_in[15];
    const float* dec_b     = (const float*)d_in[16];
    const float* fc_W      = (const float*)d_in[17];
    const float* fc_b      = (const float*)d_in[18];
    float* out = (float*)d_out;

    // indices + output t=0 zeros (independent of everything downstream)
    k_idx<<<12, 256>>>(Problem, LF);
    k_zero_t0<<<(Bz * Vv + 255) / 256, 256>>>(out);

    // x-input gate GEMMs (gathered embeddings), outputs batch-minor (mode 2)
    {
        dim3 g(G4 / 64, (Ss * Bz + 63) / 64);
        k_sgemm<<<g, 256>>>(enc_embed, enc_Wih_f, enc_b_f, nullptr,
                            Ss * Bz, G4, Ee, 0, 0, 2);
        k_sgemm<<<g, 256>>>(enc_embed, enc_Wih_b, enc_b_b, nullptr,
                            Ss * Bz, G4, Ee, 1, 1, 2);
    }
    {
        dim3 g(G4 / 64, ((Tt - 1) * Bz + 63) / 64);
        k_sgemm<<<g, 256>>>(dec_embed, dec_Wih, dec_b, nullptr,
                            (Tt - 1) * Bz, G4, Ee, 2, 2, 2);
    }

    // encoder scan (fwd + bwd fused, persistent)
    k_enc_scan<<<128, 256>>>(enc_Whh_f, enc_Whh_b);

    // bridge: h0 from hidden states, c0 from cell states (single pass)
    k_h0c0<<<64, 256>>>(Wh, bh, Wc, bc);

    // decoder scan (persistent)
    k_dec_scan<<<64, 256>>>(dec_Whh);

    // vocab projection into logits slots t=1..95 (mode 1).
    // A selected in-kernel (d_hs) via which_idx=3; host passes nullptr.
    {
        dim3 g((Vv + 63) / 64, ((Tt - 1) * Bz + 63) / 64);
        k_sgemm<<<g, 256>>>(nullptr, fc_W, fc_b, out,
                            (Tt - 1) * Bz, Vv, Hh, 3, 3, 1);
    }
}

// round 4
// speedup vs baseline: 1.0491x; 1.0491x over previous
#include <cuda_runtime.h>
#include <math.h>

// Problem constants
#define Bz 32
#define Ss 96
#define Tt 96
#define Ee 200
#define Hh 512
#define Vv 30000
#define G4 2048   // 4*H

// ---------------- scratch (device globals; no runtime allocation) ----------
__device__ float d_gxf[(size_t)Ss * G4 * Bz];        // [s][4H][b] precomputed x-gates fwd
__device__ float d_gxb[(size_t)Ss * G4 * Bz];        // [s][4H][b] bwd (time-reversed)
__device__ float d_gxd[(size_t)(Tt - 1) * G4 * Bz];  // [t][4H][b] decoder
__device__ float d_hping[2 * 2 * Hh * Bz];           // encoder h ping-pong [dir][buf][k][b]
__device__ float d_hdping[2 * Hh * Bz];              // decoder h ping-pong [buf][k][b]
__device__ float d_hfin[2 * Hh * Bz];                // final enc h [dir][k][b]
__device__ float d_cfin[2 * Hh * Bz];                // final enc c [dir][k][b]
__device__ float d_c0[Hh * Bz];                      // decoder c0 [k][b]
__device__ float d_hs[(size_t)(Tt - 1) * Bz * Hh];   // decoder hidden states [t*32+b][k]
__device__ int d_idxf[Ss * Bz];
__device__ int d_idxb[Ss * Bz];
__device__ int d_idxd[(Tt - 1) * Bz];
__device__ unsigned long long d_bar_enc;
__device__ unsigned long long d_bar_dec;

// ---------------- grid barrier (monotone counter, all CTAs resident) -------
__device__ __forceinline__ void grid_sync(unsigned long long* ctr, unsigned int nb) {
    __syncthreads();
    if (threadIdx.x == 0) {
        __threadfence();
        unsigned long long arrival = atomicAdd(ctr, 1ULL) + 1ULL;
        unsigned long long target = ((arrival + nb - 1ULL) / nb) * (unsigned long long)nb;
        while (*((volatile unsigned long long*)ctr) < target) { }
        __threadfence();
    }
    __syncthreads();
}

// ---------------- index build -------------------------------------------------
__global__ void k_idx(const int* __restrict__ Problem, const int* __restrict__ LF) {
    int m = blockIdx.x * blockDim.x + threadIdx.x;
    if (m < Ss * Bz) {
        int s = m >> 5, b = m & 31;
        d_idxf[m] = Problem[b * Ss + s];
        d_idxb[m] = Problem[b * Ss + (Ss - 1 - s)];
    }
    if (m < (Tt - 1) * Bz) {
        int t = m >> 5, b = m & 31;
        d_idxd[m] = LF[b * Tt + t];
    }
}

// ---------------- zero the t=0 output slice ----------------------------------
__global__ void k_zero_t0(float* __restrict__ out) {
    long i = (long)blockIdx.x * blockDim.x + threadIdx.x;
    if (i < (long)Bz * Vv) {
        long b = i / Vv;
        long n = i - b * Vv;
        out[b * (long)Tt * Vv + n] = 0.f;
    }
}

// ---------------- generic tiled SGEMM: C = gather(A) @ W^T + bias ------------
// A rows optionally gathered through an index array. W is [N][K] row-major.
// which_idx: 0/1/2 -> gather via d_idx{f,b,d};  3 -> A is the internal d_hs
//            symbol (selected IN-KERNEL; host passes nullptr), no gather.
// mode 0: out[m*N+n]   (plain row-major)
// mode 1: out[(m&31)][ (m>>5)+1 ][n] into (B, T, V) logits tensor
// mode 2: out[(m>>5)*N*32 + n*32 + (m&31)]  (batch-minor for scan kernels)
__global__ void __launch_bounds__(256) k_sgemm(
    const float* __restrict__ A, const float* __restrict__ W,
    const float* __restrict__ bias, float* __restrict__ out_ext,
    int M, int N, int K, int which_out, int which_idx, int mode)
{
    __shared__ float As[8][64];
    __shared__ float Bs[8][64];

    float* out = (which_out == 0) ? d_gxf : (which_out == 1) ? d_gxb
               : (which_out == 2) ? d_gxd : out_ext;
    const int* ridx = (which_idx == 0) ? d_idxf : (which_idx == 1) ? d_idxb
                    : (which_idx == 2) ? d_idxd : (const int*)0;
    // Critical: device-side selection of the hidden-state buffer. Host code
    // must NOT pass &d_hs (host shadow address) — that was the R1 bug.
    const float* Aeff = (which_idx == 3) ? (const float*)d_hs : A;

    int tid = threadIdx.x;
    int m0 = blockIdx.y * 64, n0 = blockIdx.x * 64;
    int tx = tid & 15, ty = tid >> 4;

    float acc[4][4];
#pragma unroll
    for (int i = 0; i < 4; i++)
#pragma unroll
        for (int j = 0; j < 4; j++) acc[i][j] = 0.f;

    for (int k0 = 0; k0 < K; k0 += 8) {
        if (tid < 128) {
            int mi = tid >> 1;
            int kq = (tid & 1) * 4;
            int m = m0 + mi;
            float4 v = make_float4(0.f, 0.f, 0.f, 0.f);
            if (m < M) {
                long row = ridx ? (long)ridx[m] : (long)m;
                v = *(const float4*)(Aeff + row * (long)K + k0 + kq);
            }
            As[kq + 0][mi] = v.x; As[kq + 1][mi] = v.y;
            As[kq + 2][mi] = v.z; As[kq + 3][mi] = v.w;
        } else {
            int t = tid - 128;
            int ni = t >> 1;
            int kq = (t & 1) * 4;
            int n = n0 + ni;
            float4 v = make_float4(0.f, 0.f, 0.f, 0.f);
            if (n < N) v = *(const float4*)(W + (long)n * K + k0 + kq);
            Bs[kq + 0][ni] = v.x; Bs[kq + 1][ni] = v.y;
            Bs[kq + 2][ni] = v.z; Bs[kq + 3][ni] = v.w;
        }
        __syncthreads();
#pragma unroll
        for (int kk = 0; kk < 8; kk++) {
            float4 a0 = *(const float4*)&As[kk][ty * 4];
            float4 b0 = *(const float4*)&Bs[kk][tx * 4];
            acc[0][0] += a0.x * b0.x; acc[0][1] += a0.x * b0.y; acc[0][2] += a0.x * b0.z; acc[0][3] += a0.x * b0.w;
            acc[1][0] += a0.y * b0.x; acc[1][1] += a0.y * b0.y; acc[1][2] += a0.y * b0.z; acc[1][3] += a0.y * b0.w;
            acc[2][0] += a0.z * b0.x; acc[2][1] += a0.z * b0.y; acc[2][2] += a0.z * b0.z; acc[2][3] += a0.z * b0.w;
            acc[3][0] += a0.w * b0.x; acc[3][1] += a0.w * b0.y; acc[3][2] += a0.w * b0.z; acc[3][3] += a0.w * b0.w;
        }
        __syncthreads();
    }

#pragma unroll
    for (int i = 0; i < 4; i++) {
        int m = m0 + ty * 4 + i;
        if (m >= M) continue;
#pragma unroll
        for (int j = 0; j < 4; j++) {
            int n = n0 + tx * 4 + j;
            if (n >= N) continue;
            float v = acc[i][j] + bias[n];
            if (mode == 0) {
                out[(size_t)m * N + n] = v;
            } else if (mode == 1) {
                out[((size_t)(m & 31) * Tt + (m >> 5) + 1) * (size_t)Vv + n] = v;
            } else {
                out[((size_t)(m >> 5) * N + n) * 32 + (m & 31)] = v;
            }
        }
    }
}

// ---------------- LSTM cell math ---------------------------------------------
__device__ __forceinline__ void lstm_cell(float ai, float af, float ag, float ao,
                                          float& c, float& h) {
    float si = 1.f / (1.f + expf(-ai));
    float sf = 1.f / (1.f + expf(-af));
    float so = 1.f / (1.f + expf(-ao));
    float tg = tanhf(ag);
    c = sf * c + si * tg;
    h = so * tanhf(c);
}

// ---------------- encoder scan: fwd + bwd in one persistent kernel -----------
// grid = 128 blocks x 256 threads. blocks [0,64) = fwd, [64,128) = bwd.
// warp w of a block owns hidden unit j; lane = batch b. c kept in register.
__global__ void __launch_bounds__(256) k_enc_scan(const float* __restrict__ Whf,
                                                  const float* __restrict__ Whb) {
    __shared__ float hsh[128 * Bz];  // 16 KB chunk of h, transposed [k][b]
    int dir = blockIdx.x >> 6;
    int w = threadIdx.x >> 5, b = threadIdx.x & 31;
    int j = ((blockIdx.x & 63) << 3) + w;

    const float* gx = dir ? d_gxb : d_gxf;
    const float* Whh = dir ? Whb : Whf;
    float* hbuf = d_hping + (size_t)dir * (2 * Hh * Bz);

    const float* w_i = Whh + ((size_t)(0 * Hh + j)) * Hh;
    const float* w_f = Whh + ((size_t)(1 * Hh + j)) * Hh;
    const float* w_g = Whh + ((size_t)(2 * Hh + j)) * Hh;
    const float* w_o = Whh + ((size_t)(3 * Hh + j)) * Hh;

    float c = 0.f, h = 0.f;

    for (int s = 0; s < Ss; s++) {
        const float* g0 = gx + (size_t)s * G4 * Bz;
        float ai = g0[(0 * Hh + j) * Bz + b];
        float af = g0[(1 * Hh + j) * Bz + b];
        float ag = g0[(2 * Hh + j) * Bz + b];
        float ao = g0[(3 * Hh + j) * Bz + b];

        if (s > 0) {
            const float* hcur = hbuf + (size_t)(s & 1) * Hh * Bz;
            for (int kc = 0; kc < Hh; kc += 128) {
                __syncthreads();
#pragma unroll
                for (int t = 0; t < 4; t++)
                    ((float4*)hsh)[threadIdx.x + t * 256] =
                        ((const float4*)(hcur + kc * Bz))[threadIdx.x + t * 256];
                __syncthreads();
#pragma unroll 8
                for (int k = 0; k < 128; k += 4) {
                    float4 wi = *(const float4*)(w_i + kc + k);
                    float4 wf = *(const float4*)(w_f + kc + k);
                    float4 wg = *(const float4*)(w_g + kc + k);
                    float4 wo = *(const float4*)(w_o + kc + k);
                    float h0 = hsh[(k + 0) * Bz + b];
                    float h1 = hsh[(k + 1) * Bz + b];
                    float h2 = hsh[(k + 2) * Bz + b];
                    float h3 = hsh[(k + 3) * Bz + b];
                    ai += wi.x * h0 + wi.y * h1 + wi.z * h2 + wi.w * h3;
                    af += wf.x * h0 + wf.y * h1 + wf.z * h2 + wf.w * h3;
                    ag += wg.x * h0 + wg.y * h1 + wg.z * h2 + wg.w * h3;
                    ao += wo.x * h0 + wo.y * h1 + wo.z * h2 + wo.w * h3;
                }
            }
        }
        lstm_cell(ai, af, ag, ao, c, h);
        hbuf[(size_t)((s + 1) & 1) * Hh * Bz + j * Bz + b] = h;
        grid_sync(&d_bar_enc, 128);
    }
    d_hfin[(size_t)dir * Hh * Bz + j * Bz + b] = h;
    d_cfin[(size_t)dir * Hh * Bz + j * Bz + b] = c;
}

// ---------------- bridge: h0 = [hf,hb]@Wh^T+bh ; c0 = [cf,cb]@Wc^T+bc --------
// h0 from HIDDEN states (d_hfin), c0 from CELL states (d_cfin), one pass.
__global__ void __launch_bounds__(256) k_h0c0(const float* __restrict__ Wh,
                                              const float* __restrict__ bh,
                                              const float* __restrict__ Wc,
                                              const float* __restrict__ bc) {
    int g = blockIdx.x * blockDim.x + threadIdx.x;  // 16384 threads
    int j = g >> 5, b = g & 31;
    const float* whr = Wh + (size_t)j * (2 * Hh);
    const float* wcr = Wc + (size_t)j * (2 * Hh);
    float ah = bh[j], ac = bc[j];
#pragma unroll 4
    for (int k = 0; k < 2 * Hh; k += 4) {
        float4 w1 = *(const float4*)(whr + k);
        float4 w2 = *(const float4*)(wcr + k);
        float hv0 = d_hfin[(k + 0) * Bz + b];
        float hv1 = d_hfin[(k + 1) * Bz + b];
        float hv2 = d_hfin[(k + 2) * Bz + b];
        float hv3 = d_hfin[(k + 3) * Bz + b];
        float cv0 = d_cfin[(k + 0) * Bz + b];
        float cv1 = d_cfin[(k + 1) * Bz + b];
        float cv2 = d_cfin[(k + 2) * Bz + b];
        float cv3 = d_cfin[(k + 3) * Bz + b];
        ah += w1.x * hv0 + w1.y * hv1 + w1.z * hv2 + w1.w * hv3;
        ac += w2.x * cv0 + w2.y * cv1 + w2.z * cv2 + w2.w * cv3;
    }
    d_hdping[j * Bz + b] = ah;   // decoder reads buf 0 at t=0
    d_c0[j * Bz + b] = ac;
}

// ---------------- decoder scan (persistent, 64 blocks) -----------------------
__global__ void __launch_bounds__(256) k_dec_scan(const float* __restrict__ Whh) {
    __shared__ float hsh[128 * Bz];
    int w = threadIdx.x >> 5, b = threadIdx.x & 31;
    int j = (blockIdx.x << 3) + w;

    const float* w_i = Whh + ((size_t)(0 * Hh + j)) * Hh;
    const float* w_f = Whh + ((size_t)(1 * Hh + j)) * Hh;
    const float* w_g = Whh + ((size_t)(2 * Hh + j)) * Hh;
    const float* w_o = Whh + ((size_t)(3 * Hh + j)) * Hh;

    float c = d_c0[j * Bz + b];
    float h = 0.f;

    for (int t = 0; t < Tt - 1; t++) {
        const float* g0 = d_gxd + (size_t)t * G4 * Bz;
        float ai = g0[(0 * Hh + j) * Bz + b];
        float af = g0[(1 * Hh + j) * Bz + b];
        float ag = g0[(2 * Hh + j) * Bz + b];
        float ao = g0[(3 * Hh + j) * Bz + b];

        const float* hcur = d_hdping + (size_t)(t & 1) * Hh * Bz;
        for (int kc = 0; kc < Hh; kc += 128) {
            __syncthreads();
#pragma unroll
            for (int q = 0; q < 4; q++)
                ((float4*)hsh)[threadIdx.x + q * 256] =
                    ((const float4*)(hcur + kc * Bz))[threadIdx.x + q * 256];
            __syncthreads();
#pragma unroll 8
            for (int k = 0; k < 128; k += 4) {
                float4 wi = *(const float4*)(w_i + kc + k);
                float4 wf = *(const float4*)(w_f + kc + k);
                float4 wg = *(const float4*)(w_g + kc + k);
                float4 wo = *(const float4*)(w_o + kc + k);
                float h0 = hsh[(k + 0) * Bz + b];
                float h1 = hsh[(k + 1) * Bz + b];
                float h2 = hsh[(k + 2) * Bz + b];
                float h3 = hsh[(k + 3) * Bz + b];
                ai += wi.x * h0 + wi.y * h1 + wi.z * h2 + wi.w * h3;
                af += wf.x * h0 + wf.y * h1 + wf.z * h2 + wf.w * h3;
                ag += wg.x * h0 + wg.y * h1 + wg.z * h2 + wg.w * h3;
                ao += wo.x * h0 + wo.y * h1 + wo.z * h2 + wo.w * h3;
            }
        }
        lstm_cell(ai, af, ag, ao, c, h);
        d_hdping[(size_t)((t + 1) & 1) * Hh * Bz + j * Bz + b] = h;
        d_hs[((size_t)t * Bz + b) * Hh + j] = h;
        grid_sync(&d_bar_dec, 64);
    }
}

// ---------------- launch -----------------------------------------------------
extern "C" void kernel_launch(void* const* d_in, const int* in_sizes, int n_in,
                              void* d_out, int out_size) {
    (void)in_sizes; (void)n_in; (void)out_size;
    const int*   Problem   = (const int*)d_in[0];
    const int*   LF        = (const int*)d_in[1];
    const float* enc_embed = (const float*)d_in[2];
    const float* dec_embed = (const float*)d_in[3];
    const float* enc_Wih_f = (const float*)d_in[4];
    const float* enc_Whh_f = (const float*)d_in[5];
    const float* enc_b_f   = (const float*)d_in[6];
    const float* enc_Wih_b = (const float*)d_in[7];
    const float* enc_Whh_b = (const float*)d_in[8];
    const float* enc_b_b   = (const float*)d_in[9];
    const float* Wh        = (const float*)d_in[10];
    const float* bh        = (const float*)d_in[11];
    const float* Wc        = (const float*)d_in[12];
    const float* bc        = (const float*)d_in[13];
    const float* dec_Wih   = (const float*)d_in[14];
    const float* dec_Whh   = (const float*)d_in[15];
    const float* dec_b     = (const float*)d_in[16];
    const float* fc_W      = (const float*)d_in[17];
    const float* fc_b      = (const float*)d_in[18];
    float* out = (float*)d_out;

    // indices + output t=0 zeros (independent of everything downstream)
    k_idx<<<12, 256>>>(Problem, LF);
    k_zero_t0<<<(Bz * Vv + 255) / 256, 256>>>(out);

    // x-input gate GEMMs (gathered embeddings), outputs batch-minor (mode 2)
    {
        dim3 g(G4 / 64, (Ss * Bz + 63) / 64);
        k_sgemm<<<g, 256>>>(enc_embed, enc_Wih_f, enc_b_f, nullptr,
                            Ss * Bz, G4, Ee, 0, 0, 2);
        k_sgemm<<<g, 256>>>(enc_embed, enc_Wih_b, enc_b_b, nullptr,
                            Ss * Bz, G4, Ee, 1, 1, 2);
    }
    {
        dim3 g(G4 / 64, ((Tt - 1) * Bz + 63) / 64);
        k_sgemm<<<g, 256>>>(dec_embed, dec_Wih, dec_b, nullptr,
                            (Tt - 1) * Bz, G4, Ee, 2, 2, 2);
    }

    // encoder scan (fwd + bwd fused, persistent)
    k_enc_scan<<<128, 256>>>(enc_Whh_f, enc_Whh_b);

    // bridge: h0 from hidden states, c0 from cell states (single pass)
    k_h0c0<<<64, 256>>>(Wh, bh, Wc, bc);

    // decoder scan (persistent)
    k_dec_scan<<<64, 256>>>(dec_Whh);

    // vocab projection into logits slots t=1..95 (mode 1).
    // A selected in-kernel (d_hs) via which_idx=3; host passes nullptr.
    {
        dim3 g((Vv + 63) / 64, ((Tt - 1) * Bz + 63) / 64);
        k_sgemm<<<g, 256>>>(nullptr, fc_W, fc_b, out,
                            (Tt - 1) * Bz, Vv, Hh, 3, 3, 1);
    }
}

// round 5
// speedup vs baseline: 2.6684x; 2.5434x over previous
#include <cuda_runtime.h>
#include <math.h>

#define Bz 32
#define Ss 96
#define Tt 96
#define Ee 200
#define Hh 512
#define Vv 30000
#define G4 2048

typedef unsigned long long ull;

// Pair layout for (k,b) arrays: element (k,b) at [(k*16+(b&15))*2 + (b>>4)]
__device__ float d_gxf[(size_t)Ss * G4 * Bz];
__device__ float d_gxb[(size_t)Ss * G4 * Bz];
__device__ float d_gxd[(size_t)(Tt - 1) * G4 * Bz];
__device__ float d_hping[2 * 2 * Hh * Bz];
__device__ float d_hdping[2 * Hh * Bz];
__device__ float d_hfin[2 * Hh * Bz];
__device__ float d_cfin[2 * Hh * Bz];
__device__ float d_c0[Hh * Bz];
__device__ float d_hs[(size_t)(Tt - 1) * Bz * Hh];   // row-major [t*32+b][k]
__device__ int d_idxf[Ss * Bz];
__device__ int d_idxb[Ss * Bz];
__device__ int d_idxd[(Tt - 1) * Bz];
__device__ ull d_bar_enc;
__device__ ull d_bar_dec;

__device__ __forceinline__ ull pack2(float x, float y) {
    ull r; asm("mov.b64 %0,{%1,%2};" : "=l"(r) : "f"(x), "f"(y)); return r;
}
__device__ __forceinline__ ull ffma2(ull a, ull b, ull c) {
    ull d; asm("fma.rn.f32x2 %0,%1,%2,%3;" : "=l"(d) : "l"(a), "l"(b), "l"(c)); return d;
}
__device__ __forceinline__ ull fadd2(ull a, ull b) {
    ull d; asm("add.rn.f32x2 %0,%1,%2;" : "=l"(d) : "l"(a), "l"(b)); return d;
}

__device__ __forceinline__ void grid_sync(ull* ctr, unsigned int nb) {
    __syncthreads();
    if (threadIdx.x == 0) {
        __threadfence();
        ull arrival = atomicAdd(ctr, 1ULL) + 1ULL;
        ull target = ((arrival + nb - 1ULL) / nb) * (ull)nb;
        while (*((volatile ull*)ctr) < target) { }
        __threadfence();
    }
    __syncthreads();
}

__global__ void k_idx(const int* __restrict__ Problem, const int* __restrict__ LF) {
    int m = blockIdx.x * blockDim.x + threadIdx.x;
    if (m < Ss * Bz) {
        int s = m >> 5, b = m & 31;
        d_idxf[m] = Problem[b * Ss + s];
        d_idxb[m] = Problem[b * Ss + (Ss - 1 - s)];
    }
    if (m < (Tt - 1) * Bz) {
        int t = m >> 5, b = m & 31;
        d_idxd[m] = LF[b * Tt + t];
    }
}

__global__ void k_zero_t0(float* __restrict__ out) {
    long i = (long)blockIdx.x * blockDim.x + threadIdx.x;
    if (i < (long)Bz * Vv) {
        long b = i / Vv;
        long n = i - b * Vv;
        out[b * (long)Tt * Vv + n] = 0.f;
    }
}

// x-gate SGEMM: C = gather(A) @ W^T + bias, pair-layout output
__global__ void __launch_bounds__(256) k_sgemm(
    const float* __restrict__ A, const float* __restrict__ W,
    const float* __restrict__ bias, int M, int N, int K,
    int which_out, int which_idx)
{
    __shared__ float As[8][64];
    __shared__ float Bs[8][64];
    float* out = (which_out == 0) ? d_gxf : (which_out == 1) ? d_gxb : d_gxd;
    const int* ridx = (which_idx == 0) ? d_idxf : (which_idx == 1) ? d_idxb : d_idxd;

    int tid = threadIdx.x;
    int m0 = blockIdx.y * 64, n0 = blockIdx.x * 64;
    int tx = tid & 15, ty = tid >> 4;
    float acc[4][4];
#pragma unroll
    for (int i = 0; i < 4; i++)
#pragma unroll
        for (int j = 0; j < 4; j++) acc[i][j] = 0.f;

    for (int k0 = 0; k0 < K; k0 += 8) {
        if (tid < 128) {
            int mi = tid >> 1, kq = (tid & 1) * 4, m = m0 + mi;
            float4 v = make_float4(0.f, 0.f, 0.f, 0.f);
            if (m < M) v = *(const float4*)(A + (long)ridx[m] * K + k0 + kq);
            As[kq + 0][mi] = v.x; As[kq + 1][mi] = v.y;
            As[kq + 2][mi] = v.z; As[kq + 3][mi] = v.w;
        } else {
            int t = tid - 128, ni = t >> 1, kq = (t & 1) * 4, n = n0 + ni;
            float4 v = make_float4(0.f, 0.f, 0.f, 0.f);
            if (n < N) v = *(const float4*)(W + (long)n * K + k0 + kq);
            Bs[kq + 0][ni] = v.x; Bs[kq + 1][ni] = v.y;
            Bs[kq + 2][ni] = v.z; Bs[kq + 3][ni] = v.w;
        }
        __syncthreads();
#pragma unroll
        for (int kk = 0; kk < 8; kk++) {
            float4 a0 = *(const float4*)&As[kk][ty * 4];
            float4 b0 = *(const float4*)&Bs[kk][tx * 4];
            acc[0][0] += a0.x * b0.x; acc[0][1] += a0.x * b0.y; acc[0][2] += a0.x * b0.z; acc[0][3] += a0.x * b0.w;
            acc[1][0] += a0.y * b0.x; acc[1][1] += a0.y * b0.y; acc[1][2] += a0.y * b0.z; acc[1][3] += a0.y * b0.w;
            acc[2][0] += a0.z * b0.x; acc[2][1] += a0.z * b0.y; acc[2][2] += a0.z * b0.z; acc[2][3] += a0.z * b0.w;
            acc[3][0] += a0.w * b0.x; acc[3][1] += a0.w * b0.y; acc[3][2] += a0.w * b0.z; acc[3][3] += a0.w * b0.w;
        }
        __syncthreads();
    }
#pragma unroll
    for (int i = 0; i < 4; i++) {
        int m = m0 + ty * 4 + i;
        if (m >= M) continue;
#pragma unroll
        for (int j = 0; j < 4; j++) {
            int n = n0 + tx * 4 + j;
            if (n >= N) continue;
            out[((size_t)(m >> 5) * N + n) * 32 + (m & 15) * 2 + ((m >> 4) & 1)]
                = acc[i][j] + bias[n];
        }
    }
}

__device__ __forceinline__ void lstm_cell(float ai, float af, float ag, float ao,
                                          float& c, float& h) {
    float si = 1.f / (1.f + expf(-ai));
    float sf = 1.f / (1.f + expf(-af));
    float so = 1.f / (1.f + expf(-ao));
    float tg = tanhf(ag);
    c = sf * c + si * tg;
    h = so * tanhf(c);
}

// Scan core: 8 j/block (warp w). Lane: g=l&3, kc=l>>2 for matvec; (bp=l&15,
// half=l>>4) for cell. Weights k in {kc+8*kk} in 64 regs. h staged in smem
// rows of 18 pairs (9 float4).
#define HS_ROW 9

__device__ __forceinline__ void scan_matvec(
    const float4* __restrict__ src, float4* hsh4, const ull* gshw,
    const float* wreg_dummy, float wreg[64], int tid, int g, int kc,
    ull acc[16])
{
#pragma unroll
    for (int i = 0; i < 16; i++) acc[i] = 0ULL;
#pragma unroll
    for (int ch = 0; ch < 2; ch++) {
        for (int ii = tid; ii < 2048; ii += 256)
            hsh4[(ii >> 3) * HS_ROW + (ii & 7)] = src[ch * 2048 + ii];
        __syncthreads();
        const ulonglong2* hs2 = (const ulonglong2*)hsh4;
#pragma unroll
        for (int kk2 = 0; kk2 < 32; kk2++) {
            float wv = wreg[ch * 32 + kk2];
            ull w2 = pack2(wv, wv);
            const ulonglong2* row = hs2 + (kc + (kk2 << 3)) * HS_ROW;
#pragma unroll
            for (int bq = 0; bq < 8; bq++) {
                ulonglong2 hv = row[bq];
                acc[2 * bq]     = ffma2(w2, hv.x, acc[2 * bq]);
                acc[2 * bq + 1] = ffma2(w2, hv.y, acc[2 * bq + 1]);
            }
        }
        __syncthreads();
    }
#pragma unroll
    for (int i = 0; i < 16; i++) {
        acc[i] = fadd2(acc[i], __shfl_xor_sync(0xffffffffu, acc[i], 4));
        acc[i] = fadd2(acc[i], __shfl_xor_sync(0xffffffffu, acc[i], 8));
        acc[i] = fadd2(acc[i], __shfl_xor_sync(0xffffffffu, acc[i], 16));
    }
}

__global__ void __launch_bounds__(256) k_enc_scan(const float* __restrict__ Whf,
                                                  const float* __restrict__ Whb) {
    __shared__ float4 hsh4[256 * HS_ROW];
    __shared__ ull gsh[8][4][16];
    int tid = threadIdx.x, w = tid >> 5, lane = tid & 31;
    int g = lane & 3, kc = lane >> 2;
    int bp = lane & 15, half = lane >> 4;
    int dir = blockIdx.x >> 6;
    int j = (blockIdx.x & 63) * 8 + w;

    const float* gx = dir ? d_gxb : d_gxf;
    const float* Whh = dir ? Whb : Whf;
    float* hbuf = d_hping + (size_t)dir * (2 * Hh * Bz);

    float wreg[64];
    {
        const float* wrow = Whh + ((size_t)g * Hh + j) * Hh + kc;
#pragma unroll
        for (int kk = 0; kk < 64; kk++) wreg[kk] = wrow[kk * 8];
    }
    float c = 0.f, h = 0.f;

    for (int s = 0; s < Ss; s++) {
        const float* gxs = gx + (size_t)s * G4 * Bz;
        float ga0 = gxs[(0 * Hh + j) * Bz + bp * 2 + half];
        float ga1 = gxs[(1 * Hh + j) * Bz + bp * 2 + half];
        float ga2 = gxs[(2 * Hh + j) * Bz + bp * 2 + half];
        float ga3 = gxs[(3 * Hh + j) * Bz + bp * 2 + half];

        if (s > 0) {
            ull acc[16];
            scan_matvec((const float4*)(hbuf + (size_t)(s & 1) * (Hh * Bz)),
                        hsh4, &gsh[w][0][0], 0, wreg, tid, g, kc, acc);
            if (lane < 4) {
#pragma unroll
                for (int i = 0; i < 16; i++) gsh[w][g][i] = acc[i];
            }
            __syncwarp();
            const float* gsf = (const float*)&gsh[w][0][0];
            ga0 += gsf[(0 * 16 + bp) * 2 + half];
            ga1 += gsf[(1 * 16 + bp) * 2 + half];
            ga2 += gsf[(2 * 16 + bp) * 2 + half];
            ga3 += gsf[(3 * 16 + bp) * 2 + half];
            __syncwarp();
        }
        lstm_cell(ga0, ga1, ga2, ga3, c, h);
        hbuf[(size_t)((s + 1) & 1) * (Hh * Bz) + (j * 16 + bp) * 2 + half] = h;
        grid_sync(&d_bar_enc, 128);
    }
    d_hfin[(size_t)dir * (Hh * Bz) + (j * 16 + bp) * 2 + half] = h;
    d_cfin[(size_t)dir * (Hh * Bz) + (j * 16 + bp) * 2 + half] = c;
}

__global__ void __launch_bounds__(256) k_dec_scan(const float* __restrict__ Whh) {
    __shared__ float4 hsh4[256 * HS_ROW];
    __shared__ ull gsh[8][4][16];
    int tid = threadIdx.x, w = tid >> 5, lane = tid & 31;
    int g = lane & 3, kc = lane >> 2;
    int bp = lane & 15, half = lane >> 4;
    int j = blockIdx.x * 8 + w;

    float wreg[64];
    {
        const float* wrow = Whh + ((size_t)g * Hh + j) * Hh + kc;
#pragma unroll
        for (int kk = 0; kk < 64; kk++) wreg[kk] = wrow[kk * 8];
    }
    float c = d_c0[(j * 16 + bp) * 2 + half];
    float h = 0.f;

    for (int t = 0; t < Tt - 1; t++) {
        const float* gxs = d_gxd + (size_t)t * G4 * Bz;
        float ga0 = gxs[(0 * Hh + j) * Bz + bp * 2 + half];
        float ga1 = gxs[(1 * Hh + j) * Bz + bp * 2 + half];
        float ga2 = gxs[(2 * Hh + j) * Bz + bp * 2 + half];
        float ga3 = gxs[(3 * Hh + j) * Bz + bp * 2 + half];

        ull acc[16];
        scan_matvec((const float4*)(d_hdping + (size_t)(t & 1) * (Hh * Bz)),
                    hsh4, &gsh[w][0][0], 0, wreg, tid, g, kc, acc);
        if (lane < 4) {
#pragma unroll
            for (int i = 0; i < 16; i++) gsh[w][g][i] = acc[i];
        }
        __syncwarp();
        const float* gsf = (const float*)&gsh[w][0][0];
        ga0 += gsf[(0 * 16 + bp) * 2 + half];
        ga1 += gsf[(1 * 16 + bp) * 2 + half];
        ga2 += gsf[(2 * 16 + bp) * 2 + half];
        ga3 += gsf[(3 * 16 + bp) * 2 + half];
        __syncwarp();

        lstm_cell(ga0, ga1, ga2, ga3, c, h);
        d_hdping[(size_t)((t + 1) & 1) * (Hh * Bz) + (j * 16 + bp) * 2 + half] = h;
        d_hs[((size_t)t * Bz + bp + 16 * half) * Hh + j] = h;
        grid_sync(&d_bar_dec, 64);
    }
}

// bridge: h0 from hidden states, c0 from cell states
__global__ void __launch_bounds__(256) k_h0c0(const float* __restrict__ Wh,
                                              const float* __restrict__ bh,
                                              const float* __restrict__ Wc,
                                              const float* __restrict__ bc) {
    int gg = blockIdx.x * blockDim.x + threadIdx.x;
    int j = gg >> 5, b = gg & 31;
    int bp = b & 15, hf = b >> 4;
    const float* hfp = d_hfin + bp * 2 + hf;
    const float* cfp = d_cfin + bp * 2 + hf;
    const float* whr = Wh + (size_t)j * (2 * Hh);
    const float* wcr = Wc + (size_t)j * (2 * Hh);
    float ah = bh[j], ac = bc[j];
#pragma unroll 8
    for (int k = 0; k < 2 * Hh; k++) {
        ah += whr[k] * hfp[k * 32];
        ac += wcr[k] * cfp[k * 32];
    }
    d_hdping[(j * 16 + bp) * 2 + hf] = ah;
    d_c0[(j * 16 + bp) * 2 + hf] = ac;
}

// Logits: tf32 mma.sync, 128x128 tile, BK=16 double-buffered
__global__ void __launch_bounds__(256) k_logits(const float* __restrict__ fcW,
                                                const float* __restrict__ fcb,
                                                float* __restrict__ out) {
    __shared__ float As[2][16][136];
    __shared__ float Bs[2][16][136];
    int tid = threadIdx.x, lane = tid & 31, w = tid >> 5;
    int m0 = blockIdx.y * 128, n0 = blockIdx.x * 128;
    int wm = w & 1, wn = w >> 1;

    float acc[4][4][4];
#pragma unroll
    for (int a = 0; a < 4; a++)
#pragma unroll
        for (int b = 0; b < 4; b++)
#pragma unroll
            for (int cc = 0; cc < 4; cc++) acc[a][b][cc] = 0.f;

    auto stage = [&](int q, int kb) {
#pragma unroll
        for (int r = 0; r < 2; r++) {
            int i = tid + r * 256;
            int m = i >> 2, kq = (i & 3) * 4, gm = m0 + m;
            float4 v = make_float4(0.f, 0.f, 0.f, 0.f);
            if (gm < 3040) v = *(const float4*)(d_hs + (size_t)gm * Hh + kb + kq);
            unsigned t0, t1, t2, t3;
            asm("cvt.rna.tf32.f32 %0,%1;" : "=r"(t0) : "f"(v.x));
            asm("cvt.rna.tf32.f32 %0,%1;" : "=r"(t1) : "f"(v.y));
            asm("cvt.rna.tf32.f32 %0,%1;" : "=r"(t2) : "f"(v.z));
            asm("cvt.rna.tf32.f32 %0,%1;" : "=r"(t3) : "f"(v.w));
            As[q][kq + 0][m] = __uint_as_float(t0);
            As[q][kq + 1][m] = __uint_as_float(t1);
            As[q][kq + 2][m] = __uint_as_float(t2);
            As[q][kq + 3][m] = __uint_as_float(t3);
        }
#pragma unroll
        for (int r = 0; r < 2; r++) {
            int i = tid + r * 256;
            int n = i >> 2, kq = (i & 3) * 4, gn = n0 + n;
            float4 v = make_float4(0.f, 0.f, 0.f, 0.f);
            if (gn < Vv) v = *(const float4*)(fcW + (size_t)gn * Hh + kb + kq);
            unsigned t0, t1, t2, t3;
            asm("cvt.rna.tf32.f32 %0,%1;" : "=r"(t0) : "f"(v.x));
            asm("cvt.rna.tf32.f32 %0,%1;" : "=r"(t1) : "f"(v.y));
            asm("cvt.rna.tf32.f32 %0,%1;" : "=r"(t2) : "f"(v.z));
            asm("cvt.rna.tf32.f32 %0,%1;" : "=r"(t3) : "f"(v.w));
            Bs[q][kq + 0][n] = __uint_as_float(t0);
            Bs[q][kq + 1][n] = __uint_as_float(t1);
            Bs[q][kq + 2][n] = __uint_as_float(t2);
            Bs[q][kq + 3][n] = __uint_as_float(t3);
        }
    };

    stage(0, 0);
    __syncthreads();
    for (int kt = 0; kt < 32; kt++) {
        int q = kt & 1;
        if (kt < 31) stage(q ^ 1, (kt + 1) * 16);
#pragma unroll
        for (int ks = 0; ks < 16; ks += 8) {
            int kb2 = ks + (lane & 3);
            unsigned a[4][4];
#pragma unroll
            for (int mt = 0; mt < 4; mt++) {
                int ml = wm * 64 + mt * 16 + (lane >> 2);
                a[mt][0] = __float_as_uint(As[q][kb2][ml]);
                a[mt][1] = __float_as_uint(As[q][kb2][ml + 8]);
                a[mt][2] = __float_as_uint(As[q][kb2 + 4][ml]);
                a[mt][3] = __float_as_uint(As[q][kb2 + 4][ml + 8]);
            }
#pragma unroll
            for (int nt = 0; nt < 4; nt++) {
                int nl = wn * 32 + nt * 8 + (lane >> 2);
                unsigned b0 = __float_as_uint(Bs[q][kb2][nl]);
                unsigned b1 = __float_as_uint(Bs[q][kb2 + 4][nl]);
#pragma unroll
                for (int mt = 0; mt < 4; mt++) {
                    asm volatile(
                        "mma.sync.aligned.m16n8k8.row.col.f32.tf32.tf32.f32 "
                        "{%0,%1,%2,%3},{%4,%5,%6,%7},{%8,%9},{%0,%1,%2,%3};"
                        : "+f"(acc[mt][nt][0]), "+f"(acc[mt][nt][1]),
                          "+f"(acc[mt][nt][2]), "+f"(acc[mt][nt][3])
                        : "r"(a[mt][0]), "r"(a[mt][1]), "r"(a[mt][2]), "r"(a[mt][3]),
                          "r"(b0), "r"(b1));
                }
            }
        }
        __syncthreads();
    }

#pragma unroll
    for (int mt = 0; mt < 4; mt++) {
        int mbase = m0 + wm * 64 + mt * 16 + (lane >> 2);
#pragma unroll
        for (int nt = 0; nt < 4; nt++) {
            int n = n0 + wn * 32 + nt * 8 + 2 * (lane & 3);
            if (n >= Vv) continue;
            float bias0 = fcb[n];
            float bias1 = fcb[n + 1];
#pragma unroll
            for (int rh = 0; rh < 2; rh++) {
                int m = mbase + rh * 8;
                if (m < 3040) {
                    int b = m & 31, ts = m >> 5;
                    size_t o = ((size_t)b * Tt + ts + 1) * (size_t)Vv + n;
                    out[o]     = acc[mt][nt][rh * 2 + 0] + bias0;
                    out[o + 1] = acc[mt][nt][rh * 2 + 1] + bias1;
                }
            }
        }
    }
}

extern "C" void kernel_launch(void* const* d_in, const int* in_sizes, int n_in,
                              void* d_out, int out_size) {
    (void)in_sizes; (void)n_in; (void)out_size;
    const int*   Problem   = (const int*)d_in[0];
    const int*   LF        = (const int*)d_in[1];
    const float* enc_embed = (const float*)d_in[2];
    const float* dec_embed = (const float*)d_in[3];
    const float* enc_Wih_f = (const float*)d_in[4];
    const float* enc_Whh_f = (const float*)d_in[5];
    const float* enc_b_f   = (const float*)d_in[6];
    const float* enc_Wih_b = (const float*)d_in[7];
    const float* enc_Whh_b = (const float*)d_in[8];
    const float* enc_b_b   = (const float*)d_in[9];
    const float* Wh        = (const float*)d_in[10];
    const float* bh        = (const float*)d_in[11];
    const float* Wc        = (const float*)d_in[12];
    const float* bc        = (const float*)d_in[13];
    const float* dec_Wih   = (const float*)d_in[14];
    const float* dec_Whh   = (const float*)d_in[15];
    const float* dec_b     = (const float*)d_in[16];
    const float* fc_W      = (const float*)d_in[17];
    const float* fc_b      = (const float*)d_in[18];
    float* out = (float*)d_out;

    k_idx<<<12, 256>>>(Problem, LF);
    k_zero_t0<<<(Bz * Vv + 255) / 256, 256>>>(out);

    {
        dim3 g(G4 / 64, (Ss * Bz) / 64);
        k_sgemm<<<g, 256>>>(enc_embed, enc_Wih_f, enc_b_f, Ss * Bz, G4, Ee, 0, 0);
        k_sgemm<<<g, 256>>>(enc_embed, enc_Wih_b, enc_b_b, Ss * Bz, G4, Ee, 1, 1);
    }
    {
        dim3 g(G4 / 64, ((Tt - 1) * Bz + 63) / 64);
        k_sgemm<<<g, 256>>>(dec_embed, dec_Wih, dec_b, (Tt - 1) * Bz, G4, Ee, 2, 2);
    }

    k_enc_scan<<<128, 256>>>(enc_Whh_f, enc_Whh_b);
    k_h0c0<<<64, 256>>>(Wh, bh, Wc, bc);
    k_dec_scan<<<64, 256>>>(dec_Whh);

    {
        dim3 g((Vv + 127) / 128, (3040 + 127) / 128);
        k_logits<<<g, 256>>>(fc_W, fc_b, out);
    }
}

// round 7
// speedup vs baseline: 3.1155x; 1.1675x over previous
#include <cuda_runtime.h>
#include <math.h>
#include <stdint.h>

#define Bz 32
#define Ss 96
#define Tt 96
#define Ee 200
#define Hh 512
#define Vv 30000
#define G4 2048
#define VPAD 30208   // 118 * 256
#define MPAD 3072    // 24 * 128

typedef unsigned long long ull;

// Pair layout for (k,b) arrays: element (k,b) at [(k*16+(b&15))*2 + (b>>4)]
__device__ float d_gxf[(size_t)Ss * G4 * Bz];
__device__ float d_gxb[(size_t)Ss * G4 * Bz];
__device__ float d_gxd[(size_t)(Tt - 1) * G4 * Bz];
__device__ float d_hping[2 * 2 * Hh * Bz];
__device__ float d_hdping[2 * Hh * Bz];
__device__ float d_hfin[2 * Hh * Bz];
__device__ float d_cfin[2 * Hh * Bz];
__device__ float d_c0[Hh * Bz];
__device__ float d_hs[(size_t)(Tt - 1) * Bz * Hh];   // [t*32+b][k], tf32-rounded
__device__ float d_wtf[(size_t)VPAD * Hh];           // fc_W fragment-permuted
__device__ float d_atf[(size_t)MPAD * Hh];           // d_hs fragment-permuted
__device__ int d_idxf[Ss * Bz];
__device__ int d_idxb[Ss * Bz];
__device__ int d_idxd[(Tt - 1) * Bz];
__device__ ull d_bar_enc;
__device__ ull d_bar_dec;

__device__ __forceinline__ ull pack2(float x, float y) {
    ull r; asm("mov.b64 %0,{%1,%2};" : "=l"(r) : "f"(x), "f"(y)); return r;
}
__device__ __forceinline__ ull ffma2(ull a, ull b, ull c) {
    ull d; asm("fma.rn.f32x2 %0,%1,%2,%3;" : "=l"(d) : "l"(a), "l"(b), "l"(c)); return d;
}
__device__ __forceinline__ ull fadd2(ull a, ull b) {
    ull d; asm("add.rn.f32x2 %0,%1,%2;" : "=l"(d) : "l"(a), "l"(b)); return d;
}
__device__ __forceinline__ unsigned cvt_tf32(float x) {
    unsigned u; asm("cvt.rna.tf32.f32 %0,%1;" : "=r"(u) : "f"(x)); return u;
}

__device__ __forceinline__ void grid_sync(ull* ctr, unsigned int nb) {
    __syncthreads();
    if (threadIdx.x == 0) {
        __threadfence();
        ull arrival = atomicAdd(ctr, 1ULL) + 1ULL;
        ull target = ((arrival + nb - 1ULL) / nb) * (ull)nb;
        while (*((volatile ull*)ctr) < target) { }
        __threadfence();
    }
    __syncthreads();
}

__global__ void k_idx(const int* __restrict__ Problem, const int* __restrict__ LF) {
    int m = blockIdx.x * blockDim.x + threadIdx.x;
    if (m < Ss * Bz) {
        int s = m >> 5, b = m & 31;
        d_idxf[m] = Problem[b * Ss + s];
        d_idxb[m] = Problem[b * Ss + (Ss - 1 - s)];
    }
    if (m < (Tt - 1) * Bz) {
        int t = m >> 5, b = m & 31;
        d_idxd[m] = LF[b * Tt + t];
    }
}

__global__ void k_zero_t0(float* __restrict__ out) {
    long i = (long)blockIdx.x * blockDim.x + threadIdx.x;
    if (i < (long)Bz * Vv) {
        long b = i / Vv;
        long n = i - b * Vv;
        out[b * (long)Tt * Vv + n] = 0.f;
    }
}

// ---- fc_W -> tf32, fragment-permuted, padded to VPAD --------------------
// float4 index o: lane=o&31, p=(o>>5)&3, ks=(o>>7)&63, wn=(o>>13)&3, ntile=o>>15
// element: n0 = ntile*256 + wn*64 + p*16 + (lane>>2), kl = ks*8 + (lane&3)
// float4 = { W[n0][kl], W[n0][kl+4], W[n0+8][kl], W[n0+8][kl+4] }
__global__ void __launch_bounds__(256) k_permW(const float* __restrict__ W) {
    int o = blockIdx.x * 256 + threadIdx.x;   // 15104*256 = VPAD*Hh/4 exactly
    int lane = o & 31;
    int p = (o >> 5) & 3;
    int ks = (o >> 7) & 63;
    int wn = (o >> 13) & 3;
    int ntile = o >> 15;
    int n0 = ntile * 256 + wn * 64 + p * 16 + (lane >> 2);
    int kl = ks * 8 + (lane & 3);
    float4 v = make_float4(0.f, 0.f, 0.f, 0.f);
    if (n0 < Vv) {
        v.x = W[(size_t)n0 * Hh + kl];
        v.y = W[(size_t)n0 * Hh + kl + 4];
    }
    if (n0 + 8 < Vv) {
        v.z = W[(size_t)(n0 + 8) * Hh + kl];
        v.w = W[(size_t)(n0 + 8) * Hh + kl + 4];
    }
    v.x = __uint_as_float(cvt_tf32(v.x));
    v.y = __uint_as_float(cvt_tf32(v.y));
    v.z = __uint_as_float(cvt_tf32(v.z));
    v.w = __uint_as_float(cvt_tf32(v.w));
    ((float4*)d_wtf)[o] = v;
}

// ---- d_hs -> fragment-permuted A, padded to MPAD ------------------------
// float4 index o: lane=o&31, mt=(o>>5)&3, ks=(o>>7)&63, wm=(o>>13)&1, mtile=o>>14
// m0 = mtile*128 + wm*64 + mt*16 + (lane>>2), kl = ks*8+(lane&3)
// float4 = { A[m0][kl], A[m0+8][kl], A[m0][kl+4], A[m0+8][kl+4] }  (a0,a1,a2,a3)
__global__ void __launch_bounds__(256) k_permA() {
    int o = blockIdx.x * 256 + threadIdx.x;   // 1536*256 = MPAD*Hh/4 exactly
    int lane = o & 31;
    int mt = (o >> 5) & 3;
    int ks = (o >> 7) & 63;
    int wm = (o >> 13) & 1;
    int mtile = o >> 14;
    int m0 = mtile * 128 + wm * 64 + mt * 16 + (lane >> 2);
    int kl = ks * 8 + (lane & 3);
    float4 v = make_float4(0.f, 0.f, 0.f, 0.f);
    if (m0 < 3040) {
        v.x = d_hs[(size_t)m0 * Hh + kl];
        v.z = d_hs[(size_t)m0 * Hh + kl + 4];
    }
    if (m0 + 8 < 3040) {
        v.y = d_hs[(size_t)(m0 + 8) * Hh + kl];
        v.w = d_hs[(size_t)(m0 + 8) * Hh + kl + 4];
    }
    ((float4*)d_atf)[o] = v;
}

// x-gate SGEMM: C = gather(A) @ W^T + bias, pair-layout output
__global__ void __launch_bounds__(256) k_sgemm(
    const float* __restrict__ A, const float* __restrict__ W,
    const float* __restrict__ bias, int M, int N, int K,
    int which_out, int which_idx)
{
    __shared__ float As[8][64];
    __shared__ float Bs[8][64];
    float* out = (which_out == 0) ? d_gxf : (which_out == 1) ? d_gxb : d_gxd;
    const int* ridx = (which_idx == 0) ? d_idxf : (which_idx == 1) ? d_idxb : d_idxd;

    int tid = threadIdx.x;
    int m0 = blockIdx.y * 64, n0 = blockIdx.x * 64;
    int tx = tid & 15, ty = tid >> 4;
    float acc[4][4];
#pragma unroll
    for (int i = 0; i < 4; i++)
#pragma unroll
        for (int j = 0; j < 4; j++) acc[i][j] = 0.f;

    for (int k0 = 0; k0 < K; k0 += 8) {
        if (tid < 128) {
            int mi = tid >> 1, kq = (tid & 1) * 4, m = m0 + mi;
            float4 v = make_float4(0.f, 0.f, 0.f, 0.f);
            if (m < M) v = *(const float4*)(A + (long)ridx[m] * K + k0 + kq);
            As[kq + 0][mi] = v.x; As[kq + 1][mi] = v.y;
            As[kq + 2][mi] = v.z; As[kq + 3][mi] = v.w;
        } else {
            int t = tid - 128, ni = t >> 1, kq = (t & 1) * 4, n = n0 + ni;
            float4 v = make_float4(0.f, 0.f, 0.f, 0.f);
            if (n < N) v = *(const float4*)(W + (long)n * K + k0 + kq);
            Bs[kq + 0][ni] = v.x; Bs[kq + 1][ni] = v.y;
            Bs[kq + 2][ni] = v.z; Bs[kq + 3][ni] = v.w;
        }
        __syncthreads();
#pragma unroll
        for (int kk = 0; kk < 8; kk++) {
            float4 a0 = *(const float4*)&As[kk][ty * 4];
            float4 b0 = *(const float4*)&Bs[kk][tx * 4];
            acc[0][0] += a0.x * b0.x; acc[0][1] += a0.x * b0.y; acc[0][2] += a0.x * b0.z; acc[0][3] += a0.x * b0.w;
            acc[1][0] += a0.y * b0.x; acc[1][1] += a0.y * b0.y; acc[1][2] += a0.y * b0.z; acc[1][3] += a0.y * b0.w;
            acc[2][0] += a0.z * b0.x; acc[2][1] += a0.z * b0.y; acc[2][2] += a0.z * b0.z; acc[2][3] += a0.z * b0.w;
            acc[3][0] += a0.w * b0.x; acc[3][1] += a0.w * b0.y; acc[3][2] += a0.w * b0.z; acc[3][3] += a0.w * b0.w;
        }
        __syncthreads();
    }
#pragma unroll
    for (int i = 0; i < 4; i++) {
        int m = m0 + ty * 4 + i;
        if (m >= M) continue;
#pragma unroll
        for (int j = 0; j < 4; j++) {
            int n = n0 + tx * 4 + j;
            if (n >= N) continue;
            out[((size_t)(m >> 5) * N + n) * 32 + (m & 15) * 2 + ((m >> 4) & 1)]
                = acc[i][j] + bias[n];
        }
    }
}

__device__ __forceinline__ void lstm_cell(float ai, float af, float ag, float ao,
                                          float& c, float& h) {
    float si = 1.f / (1.f + expf(-ai));
    float sf = 1.f / (1.f + expf(-af));
    float so = 1.f / (1.f + expf(-ao));
    float tg = tanhf(ag);
    c = sf * c + si * tg;
    h = so * tanhf(c);
}

#define HS_ROW 9

__device__ __forceinline__ void scan_matvec(
    const float4* __restrict__ src, float4* hsh4, float wreg[64],
    int tid, int kc, ull acc[16])
{
#pragma unroll
    for (int i = 0; i < 16; i++) acc[i] = 0ULL;
#pragma unroll
    for (int ch = 0; ch < 2; ch++) {
        for (int ii = tid; ii < 2048; ii += 256)
            hsh4[(ii >> 3) * HS_ROW + (ii & 7)] = src[ch * 2048 + ii];
        __syncthreads();
        const ulonglong2* hs2 = (const ulonglong2*)hsh4;
#pragma unroll
        for (int kk2 = 0; kk2 < 32; kk2++) {
            float wv = wreg[ch * 32 + kk2];
            ull w2 = pack2(wv, wv);
            const ulonglong2* row = hs2 + (kc + (kk2 << 3)) * HS_ROW;
#pragma unroll
            for (int bq = 0; bq < 8; bq++) {
                ulonglong2 hv = row[bq];
                acc[2 * bq]     = ffma2(w2, hv.x, acc[2 * bq]);
                acc[2 * bq + 1] = ffma2(w2, hv.y, acc[2 * bq + 1]);
            }
        }
        __syncthreads();
    }
#pragma unroll
    for (int i = 0; i < 16; i++) {
        acc[i] = fadd2(acc[i], __shfl_xor_sync(0xffffffffu, acc[i], 4));
        acc[i] = fadd2(acc[i], __shfl_xor_sync(0xffffffffu, acc[i], 8));
        acc[i] = fadd2(acc[i], __shfl_xor_sync(0xffffffffu, acc[i], 16));
    }
}

__global__ void __launch_bounds__(256) k_enc_scan(const float* __restrict__ Whf,
                                                  const float* __restrict__ Whb) {
    __shared__ float4 hsh4[256 * HS_ROW];
    __shared__ ull gsh[8][4][16];
    int tid = threadIdx.x, w = tid >> 5, lane = tid & 31;
    int g = lane & 3, kc = lane >> 2;
    int bp = lane & 15, half = lane >> 4;
    int dir = blockIdx.x >> 6;
    int j = (blockIdx.x & 63) * 8 + w;

    const float* gx = dir ? d_gxb : d_gxf;
    const float* Whh = dir ? Whb : Whf;
    float* hbuf = d_hping + (size_t)dir * (2 * Hh * Bz);

    float wreg[64];
    {
        const float* wrow = Whh + ((size_t)g * Hh + j) * Hh + kc;
#pragma unroll
        for (int kk = 0; kk < 64; kk++) wreg[kk] = wrow[kk * 8];
    }
    float c = 0.f, h = 0.f;

    for (int s = 0; s < Ss; s++) {
        const float* gxs = gx + (size_t)s * G4 * Bz;
        float ga0 = gxs[(0 * Hh + j) * Bz + bp * 2 + half];
        float ga1 = gxs[(1 * Hh + j) * Bz + bp * 2 + half];
        float ga2 = gxs[(2 * Hh + j) * Bz + bp * 2 + half];
        float ga3 = gxs[(3 * Hh + j) * Bz + bp * 2 + half];

        if (s > 0) {
            ull acc[16];
            scan_matvec((const float4*)(hbuf + (size_t)(s & 1) * (Hh * Bz)),
                        hsh4, wreg, tid, kc, acc);
            if (lane < 4) {
#pragma unroll
                for (int i = 0; i < 16; i++) gsh[w][g][i] = acc[i];
            }
            __syncwarp();
            const float* gsf = (const float*)&gsh[w][0][0];
            ga0 += gsf[(0 * 16 + bp) * 2 + half];
            ga1 += gsf[(1 * 16 + bp) * 2 + half];
            ga2 += gsf[(2 * 16 + bp) * 2 + half];
            ga3 += gsf[(3 * 16 + bp) * 2 + half];
            __syncwarp();
        }
        lstm_cell(ga0, ga1, ga2, ga3, c, h);
        hbuf[(size_t)((s + 1) & 1) * (Hh * Bz) + (j * 16 + bp) * 2 + half] = h;
        grid_sync(&d_bar_enc, 128);
    }
    d_hfin[(size_t)dir * (Hh * Bz) + (j * 16 + bp) * 2 + half] = h;
    d_cfin[(size_t)dir * (Hh * Bz) + (j * 16 + bp) * 2 + half] = c;
}

__global__ void __launch_bounds__(256) k_dec_scan(const float* __restrict__ Whh) {
    __shared__ float4 hsh4[256 * HS_ROW];
    __shared__ ull gsh[8][4][16];
    int tid = threadIdx.x, w = tid >> 5, lane = tid & 31;
    int g = lane & 3, kc = lane >> 2;
    int bp = lane & 15, half = lane >> 4;
    int j = blockIdx.x * 8 + w;

    float wreg[64];
    {
        const float* wrow = Whh + ((size_t)g * Hh + j) * Hh + kc;
#pragma unroll
        for (int kk = 0; kk < 64; kk++) wreg[kk] = wrow[kk * 8];
    }
    float c = d_c0[(j * 16 + bp) * 2 + half];
    float h = 0.f;

    for (int t = 0; t < Tt - 1; t++) {
        const float* gxs = d_gxd + (size_t)t * G4 * Bz;
        float ga0 = gxs[(0 * Hh + j) * Bz + bp * 2 + half];
        float ga1 = gxs[(1 * Hh + j) * Bz + bp * 2 + half];
        float ga2 = gxs[(2 * Hh + j) * Bz + bp * 2 + half];
        float ga3 = gxs[(3 * Hh + j) * Bz + bp * 2 + half];

        ull acc[16];
        scan_matvec((const float4*)(d_hdping + (size_t)(t & 1) * (Hh * Bz)),
                    hsh4, wreg, tid, kc, acc);
        if (lane < 4) {
#pragma unroll
            for (int i = 0; i < 16; i++) gsh[w][g][i] = acc[i];
        }
        __syncwarp();
        const float* gsf = (const float*)&gsh[w][0][0];
        ga0 += gsf[(0 * 16 + bp) * 2 + half];
        ga1 += gsf[(1 * 16 + bp) * 2 + half];
        ga2 += gsf[(2 * 16 + bp) * 2 + half];
        ga3 += gsf[(3 * 16 + bp) * 2 + half];
        __syncwarp();

        lstm_cell(ga0, ga1, ga2, ga3, c, h);
        d_hdping[(size_t)((t + 1) & 1) * (Hh * Bz) + (j * 16 + bp) * 2 + half] = h;
        // store tf32-rounded for the tensor-core logits GEMM
        d_hs[((size_t)t * Bz + bp + 16 * half) * Hh + j] = __uint_as_float(cvt_tf32(h));
        grid_sync(&d_bar_dec, 64);
    }
}

__global__ void __launch_bounds__(256) k_h0c0(const float* __restrict__ Wh,
                                              const float* __restrict__ bh,
                                              const float* __restrict__ Wc,
                                              const float* __restrict__ bc) {
    int gg = blockIdx.x * blockDim.x + threadIdx.x;
    int j = gg >> 5, b = gg & 31;
    int bp = b & 15, hf = b >> 4;
    const float* hfp = d_hfin + bp * 2 + hf;
    const float* cfp = d_cfin + bp * 2 + hf;
    const float* whr = Wh + (size_t)j * (2 * Hh);
    const float* wcr = Wc + (size_t)j * (2 * Hh);
    float ah = bh[j], ac = bc[j];
#pragma unroll 8
    for (int k = 0; k < 2 * Hh; k++) {
        ah += whr[k] * hfp[k * 32];
        ac += wcr[k] * cfp[k * 32];
    }
    d_hdping[(j * 16 + bp) * 2 + hf] = ah;
    d_c0[(j * 16 + bp) * 2 + hf] = ac;
}

// =====================================================================
// Logits: register-fragment tf32 mma.sync. CTA 128m x 256n, warp 64x64.
// No shared memory, no syncthreads; operands pre-permuted in d_atf/d_wtf.
// =====================================================================
#define MMA_TF32(c0, c1, c2, c3, A0, A1, A2, A3, B0, B1) \
    asm volatile( \
        "mma.sync.aligned.m16n8k8.row.col.f32.tf32.tf32.f32 " \
        "{%0,%1,%2,%3},{%4,%5,%6,%7},{%8,%9},{%0,%1,%2,%3};" \
        : "+f"(c0), "+f"(c1), "+f"(c2), "+f"(c3) \
        : "r"(A0), "r"(A1), "r"(A2), "r"(A3), "r"(B0), "r"(B1))

__global__ void __launch_bounds__(256, 1) k_logits_f(const float* __restrict__ fcb,
                                                     float* __restrict__ out) {
    int tid = threadIdx.x, w = tid >> 5, lane = tid & 31;
    int wm = w & 1, wn = w >> 1;
    int mtile = blockIdx.y, ntile = blockIdx.x;

    const float4* Ab = (const float4*)d_atf + (size_t)(mtile * 2 + wm) * 8192 + lane;
    const float4* Bb = (const float4*)d_wtf + (size_t)(ntile * 4 + wn) * 8192 + lane;

    float acc[4][8][4];
#pragma unroll
    for (int a = 0; a < 4; a++)
#pragma unroll
        for (int b = 0; b < 8; b++)
#pragma unroll
            for (int cc = 0; cc < 4; cc++) acc[a][b][cc] = 0.f;

    float4 av[2][4], bv[2][4];
#pragma unroll
    for (int q = 0; q < 4; q++) {
        av[0][q] = Ab[q * 32];
        bv[0][q] = Bb[q * 32];
    }

    for (int ks = 0; ks < 64; ks++) {
        int cur = ks & 1, nxt = cur ^ 1;
        if (ks < 63) {
            const float4* An = Ab + (ks + 1) * 128;
            const float4* Bn = Bb + (ks + 1) * 128;
#pragma unroll
            for (int q = 0; q < 4; q++) {
                av[nxt][q] = An[q * 32];
                bv[nxt][q] = Bn[q * 32];
            }
        }
#pragma unroll
        for (int mt = 0; mt < 4; mt++) {
            unsigned a0 = __float_as_uint(av[cur][mt].x);
            unsigned a1 = __float_as_uint(av[cur][mt].y);
            unsigned a2 = __float_as_uint(av[cur][mt].z);
            unsigned a3 = __float_as_uint(av[cur][mt].w);
#pragma unroll
            for (int p = 0; p < 4; p++) {
                unsigned b0 = __float_as_uint(bv[cur][p].x);
                unsigned b1 = __float_as_uint(bv[cur][p].y);
                unsigned b2 = __float_as_uint(bv[cur][p].z);
                unsigned b3 = __float_as_uint(bv[cur][p].w);
                MMA_TF32(acc[mt][2 * p][0], acc[mt][2 * p][1],
                         acc[mt][2 * p][2], acc[mt][2 * p][3],
                         a0, a1, a2, a3, b0, b1);
                MMA_TF32(acc[mt][2 * p + 1][0], acc[mt][2 * p + 1][1],
                         acc[mt][2 * p + 1][2], acc[mt][2 * p + 1][3],
                         a0, a1, a2, a3, b2, b3);
            }
        }
    }

    int mb = mtile * 128 + wm * 64;
    int nb = ntile * 256 + wn * 64;
#pragma unroll
    for (int mt = 0; mt < 4; mt++) {
        int r0 = mb + mt * 16 + (lane >> 2);
#pragma unroll
        for (int nt = 0; nt < 8; nt++) {
            int n = nb + nt * 8 + (lane & 3) * 2;
            if (n >= Vv) continue;
            float b0 = fcb[n];
            float b1 = fcb[n + 1];
#pragma unroll
            for (int rh = 0; rh < 2; rh++) {
                int m = r0 + rh * 8;
                if (m < 3040) {
                    int b = m & 31, ts = m >> 5;
                    size_t o = ((size_t)b * Tt + ts + 1) * (size_t)Vv + n;
                    out[o]     = acc[mt][nt][rh * 2 + 0] + b0;
                    out[o + 1] = acc[mt][nt][rh * 2 + 1] + b1;
                }
            }
        }
    }
}

extern "C" void kernel_launch(void* const* d_in, const int* in_sizes, int n_in,
                              void* d_out, int out_size) {
    (void)in_sizes; (void)n_in; (void)out_size;
    const int*   Problem   = (const int*)d_in[0];
    const int*   LF        = (const int*)d_in[1];
    const float* enc_embed = (const float*)d_in[2];
    const float* dec_embed = (const float*)d_in[3];
    const float* enc_Wih_f = (const float*)d_in[4];
    const float* enc_Whh_f = (const float*)d_in[5];
    const float* enc_b_f   = (const float*)d_in[6];
    const float* enc_Wih_b = (const float*)d_in[7];
    const float* enc_Whh_b = (const float*)d_in[8];
    const float* enc_b_b   = (const float*)d_in[9];
    const float* Wh        = (const float*)d_in[10];
    const float* bh        = (const float*)d_in[11];
    const float* Wc        = (const float*)d_in[12];
    const float* bc        = (const float*)d_in[13];
    const float* dec_Wih   = (const float*)d_in[14];
    const float* dec_Whh   = (const float*)d_in[15];
    const float* dec_b     = (const float*)d_in[16];
    const float* fc_W      = (const float*)d_in[17];
    const float* fc_b      = (const float*)d_in[18];
    float* out = (float*)d_out;

    k_idx<<<12, 256>>>(Problem, LF);
    k_zero_t0<<<(Bz * Vv + 255) / 256, 256>>>(out);
    k_permW<<<VPAD * Hh / 4 / 256, 256>>>(fc_W);

    {
        dim3 g(G4 / 64, (Ss * Bz) / 64);
        k_sgemm<<<g, 256>>>(enc_embed, enc_Wih_f, enc_b_f, Ss * Bz, G4, Ee, 0, 0);
        k_sgemm<<<g, 256>>>(enc_embed, enc_Wih_b, enc_b_b, Ss * Bz, G4, Ee, 1, 1);
    }
    {
        dim3 g(G4 / 64, ((Tt - 1) * Bz + 63) / 64);
        k_sgemm<<<g, 256>>>(dec_embed, dec_Wih, dec_b, (Tt - 1) * Bz, G4, Ee, 2, 2);
    }

    k_enc_scan<<<128, 256>>>(enc_Whh_f, enc_Whh_b);
    k_h0c0<<<64, 256>>>(Wh, bh, Wc, bc);
    k_dec_scan<<<64, 256>>>(dec_Whh);
    k_permA<<<MPAD * Hh / 4 / 256, 256>>>();

    {
        dim3 g(VPAD / 256, MPAD / 128);   // 118 x 24
        k_logits_f<<<g, 256>>>(fc_b, out);
    }
}

// round 8
// speedup vs baseline: 3.5455x; 1.1380x over previous
#include <cuda_runtime.h>
#include <math.h>
#include <stdint.h>

#define Bz 32
#define Ss 96
#define Tt 96
#define Ee 200
#define Hh 512
#define Vv 30000
#define G4 2048
#define VPAD 30208   // 118 * 256
#define MPAD 3072    // 24 * 128

typedef unsigned long long ull;

// Pair layout for (k,b) arrays: element (k,b) at [(k*16+(b&15))*2 + (b>>4)]
__device__ float d_gxf[(size_t)Ss * G4 * Bz];
__device__ float d_gxb[(size_t)Ss * G4 * Bz];
__device__ float d_gxd[(size_t)(Tt - 1) * G4 * Bz];
__device__ float d_hping[2 * 2 * Hh * Bz];
__device__ float d_hdping[2 * Hh * Bz];
__device__ float d_hfin[2 * Hh * Bz];
__device__ float d_cfin[2 * Hh * Bz];
__device__ float d_c0[Hh * Bz];
__device__ float d_hs[(size_t)(Tt - 1) * Bz * Hh];   // [t*32+b][k], tf32-rounded
__device__ float d_wtf[(size_t)VPAD * Hh];           // fc_W fragment-permuted
__device__ float d_atf[(size_t)MPAD * Hh];           // d_hs fragment-permuted
__device__ int d_idxf[Ss * Bz];
__device__ int d_idxb[Ss * Bz];
__device__ int d_idxd[(Tt - 1) * Bz];
__device__ ull d_bar_enc;
__device__ ull d_bar_dec;

__device__ __forceinline__ ull pack2(float x, float y) {
    ull r; asm("mov.b64 %0,{%1,%2};" : "=l"(r) : "f"(x), "f"(y)); return r;
}
__device__ __forceinline__ ull ffma2(ull a, ull b, ull c) {
    ull d; asm("fma.rn.f32x2 %0,%1,%2,%3;" : "=l"(d) : "l"(a), "l"(b), "l"(c)); return d;
}
__device__ __forceinline__ ull fadd2(ull a, ull b) {
    ull d; asm("add.rn.f32x2 %0,%1,%2;" : "=l"(d) : "l"(a), "l"(b)); return d;
}
__device__ __forceinline__ unsigned cvt_tf32(float x) {
    unsigned u; asm("cvt.rna.tf32.f32 %0,%1;" : "=r"(u) : "f"(x)); return u;
}

__device__ __forceinline__ void grid_sync(ull* ctr, unsigned int nb) {
    __syncthreads();
    if (threadIdx.x == 0) {
        __threadfence();
        ull arrival = atomicAdd(ctr, 1ULL) + 1ULL;
        ull target = ((arrival + nb - 1ULL) / nb) * (ull)nb;
        while (*((volatile ull*)ctr) < target) { }
        __threadfence();
    }
    __syncthreads();
}

__global__ void k_idx(const int* __restrict__ Problem, const int* __restrict__ LF) {
    int m = blockIdx.x * blockDim.x + threadIdx.x;
    if (m < Ss * Bz) {
        int s = m >> 5, b = m & 31;
        d_idxf[m] = Problem[b * Ss + s];
        d_idxb[m] = Problem[b * Ss + (Ss - 1 - s)];
    }
    if (m < (Tt - 1) * Bz) {
        int t = m >> 5, b = m & 31;
        d_idxd[m] = LF[b * Tt + t];
    }
}

__global__ void k_zero_t0(float* __restrict__ out) {
    long i = (long)blockIdx.x * blockDim.x + threadIdx.x;
    if (i < (long)Bz * Vv) {
        long b = i / Vv;
        long n = i - b * Vv;
        out[b * (long)Tt * Vv + n] = 0.f;
    }
}

// ---- fc_W -> tf32, fragment-permuted, padded to VPAD --------------------
__global__ void __launch_bounds__(256) k_permW(const float* __restrict__ W) {
    int o = blockIdx.x * 256 + threadIdx.x;
    int lane = o & 31;
    int p = (o >> 5) & 3;
    int ks = (o >> 7) & 63;
    int wn = (o >> 13) & 3;
    int ntile = o >> 15;
    int n0 = ntile * 256 + wn * 64 + p * 16 + (lane >> 2);
    int kl = ks * 8 + (lane & 3);
    float4 v = make_float4(0.f, 0.f, 0.f, 0.f);
    if (n0 < Vv) {
        v.x = W[(size_t)n0 * Hh + kl];
        v.y = W[(size_t)n0 * Hh + kl + 4];
    }
    if (n0 + 8 < Vv) {
        v.z = W[(size_t)(n0 + 8) * Hh + kl];
        v.w = W[(size_t)(n0 + 8) * Hh + kl + 4];
    }
    v.x = __uint_as_float(cvt_tf32(v.x));
    v.y = __uint_as_float(cvt_tf32(v.y));
    v.z = __uint_as_float(cvt_tf32(v.z));
    v.w = __uint_as_float(cvt_tf32(v.w));
    ((float4*)d_wtf)[o] = v;
}

// ---- d_hs -> fragment-permuted A, padded to MPAD ------------------------
__global__ void __launch_bounds__(256) k_permA() {
    int o = blockIdx.x * 256 + threadIdx.x;
    int lane = o & 31;
    int mt = (o >> 5) & 3;
    int ks = (o >> 7) & 63;
    int wm = (o >> 13) & 1;
    int mtile = o >> 14;
    int m0 = mtile * 128 + wm * 64 + mt * 16 + (lane >> 2);
    int kl = ks * 8 + (lane & 3);
    float4 v = make_float4(0.f, 0.f, 0.f, 0.f);
    if (m0 < 3040) {
        v.x = d_hs[(size_t)m0 * Hh + kl];
        v.z = d_hs[(size_t)m0 * Hh + kl + 4];
    }
    if (m0 + 8 < 3040) {
        v.y = d_hs[(size_t)(m0 + 8) * Hh + kl];
        v.w = d_hs[(size_t)(m0 + 8) * Hh + kl + 4];
    }
    ((float4*)d_atf)[o] = v;
}

// x-gate SGEMM: C = gather(A) @ W^T + bias, pair-layout output
__global__ void __launch_bounds__(256) k_sgemm(
    const float* __restrict__ A, const float* __restrict__ W,
    const float* __restrict__ bias, int M, int N, int K,
    int which_out, int which_idx)
{
    __shared__ float As[8][64];
    __shared__ float Bs[8][64];
    float* out = (which_out == 0) ? d_gxf : (which_out == 1) ? d_gxb : d_gxd;
    const int* ridx = (which_idx == 0) ? d_idxf : (which_idx == 1) ? d_idxb : d_idxd;

    int tid = threadIdx.x;
    int m0 = blockIdx.y * 64, n0 = blockIdx.x * 64;
    int tx = tid & 15, ty = tid >> 4;
    float acc[4][4];
#pragma unroll
    for (int i = 0; i < 4; i++)
#pragma unroll
        for (int j = 0; j < 4; j++) acc[i][j] = 0.f;

    for (int k0 = 0; k0 < K; k0 += 8) {
        if (tid < 128) {
            int mi = tid >> 1, kq = (tid & 1) * 4, m = m0 + mi;
            float4 v = make_float4(0.f, 0.f, 0.f, 0.f);
            if (m < M) v = *(const float4*)(A + (long)ridx[m] * K + k0 + kq);
            As[kq + 0][mi] = v.x; As[kq + 1][mi] = v.y;
            As[kq + 2][mi] = v.z; As[kq + 3][mi] = v.w;
        } else {
            int t = tid - 128, ni = t >> 1, kq = (t & 1) * 4, n = n0 + ni;
            float4 v = make_float4(0.f, 0.f, 0.f, 0.f);
            if (n < N) v = *(const float4*)(W + (long)n * K + k0 + kq);
            Bs[kq + 0][ni] = v.x; Bs[kq + 1][ni] = v.y;
            Bs[kq + 2][ni] = v.z; Bs[kq + 3][ni] = v.w;
        }
        __syncthreads();
#pragma unroll
        for (int kk = 0; kk < 8; kk++) {
            float4 a0 = *(const float4*)&As[kk][ty * 4];
            float4 b0 = *(const float4*)&Bs[kk][tx * 4];
            acc[0][0] += a0.x * b0.x; acc[0][1] += a0.x * b0.y; acc[0][2] += a0.x * b0.z; acc[0][3] += a0.x * b0.w;
            acc[1][0] += a0.y * b0.x; acc[1][1] += a0.y * b0.y; acc[1][2] += a0.y * b0.z; acc[1][3] += a0.y * b0.w;
            acc[2][0] += a0.z * b0.x; acc[2][1] += a0.z * b0.y; acc[2][2] += a0.z * b0.z; acc[2][3] += a0.z * b0.w;
            acc[3][0] += a0.w * b0.x; acc[3][1] += a0.w * b0.y; acc[3][2] += a0.w * b0.z; acc[3][3] += a0.w * b0.w;
        }
        __syncthreads();
    }
#pragma unroll
    for (int i = 0; i < 4; i++) {
        int m = m0 + ty * 4 + i;
        if (m >= M) continue;
#pragma unroll
        for (int j = 0; j < 4; j++) {
            int n = n0 + tx * 4 + j;
            if (n >= N) continue;
            out[((size_t)(m >> 5) * N + n) * 32 + (m & 15) * 2 + ((m >> 4) & 1)]
                = acc[i][j] + bias[n];
        }
    }
}

__device__ __forceinline__ void lstm_cell(float ai, float af, float ag, float ao,
                                          float& c, float& h) {
    float si = 1.f / (1.f + expf(-ai));
    float sf = 1.f / (1.f + expf(-af));
    float so = 1.f / (1.f + expf(-ao));
    float tg = tanhf(ag);
    c = sf * c + si * tg;
    h = so * tanhf(c);
}

#define HS_ROW 9

// full-batch matvec (encoder: 1 warp per j, 16 pairs)
__device__ __forceinline__ void scan_matvec(
    const float4* __restrict__ src, float4* hsh4, float wreg[64],
    int tid, int kc, ull acc[16])
{
#pragma unroll
    for (int i = 0; i < 16; i++) acc[i] = 0ULL;
#pragma unroll
    for (int ch = 0; ch < 2; ch++) {
        for (int ii = tid; ii < 2048; ii += 256)
            hsh4[(ii >> 3) * HS_ROW + (ii & 7)] = src[ch * 2048 + ii];
        __syncthreads();
        const ulonglong2* hs2 = (const ulonglong2*)hsh4;
#pragma unroll
        for (int kk2 = 0; kk2 < 32; kk2++) {
            float wv = wreg[ch * 32 + kk2];
            ull w2 = pack2(wv, wv);
            const ulonglong2* row = hs2 + (kc + (kk2 << 3)) * HS_ROW;
#pragma unroll
            for (int bq = 0; bq < 8; bq++) {
                ulonglong2 hv = row[bq];
                acc[2 * bq]     = ffma2(w2, hv.x, acc[2 * bq]);
                acc[2 * bq + 1] = ffma2(w2, hv.y, acc[2 * bq + 1]);
            }
        }
        __syncthreads();
    }
#pragma unroll
    for (int i = 0; i < 16; i++) {
        acc[i] = fadd2(acc[i], __shfl_xor_sync(0xffffffffu, acc[i], 4));
        acc[i] = fadd2(acc[i], __shfl_xor_sync(0xffffffffu, acc[i], 8));
        acc[i] = fadd2(acc[i], __shfl_xor_sync(0xffffffffu, acc[i], 16));
    }
}

__global__ void __launch_bounds__(256) k_enc_scan(const float* __restrict__ Whf,
                                                  const float* __restrict__ Whb) {
    __shared__ float4 hsh4[256 * HS_ROW];
    __shared__ ull gsh[8][4][16];
    int tid = threadIdx.x, w = tid >> 5, lane = tid & 31;
    int g = lane & 3, kc = lane >> 2;
    int bp = lane & 15, half = lane >> 4;
    int dir = blockIdx.x >> 6;
    int j = (blockIdx.x & 63) * 8 + w;

    const float* gx = dir ? d_gxb : d_gxf;
    const float* Whh = dir ? Whb : Whf;
    float* hbuf = d_hping + (size_t)dir * (2 * Hh * Bz);

    float wreg[64];
    {
        const float* wrow = Whh + ((size_t)g * Hh + j) * Hh + kc;
#pragma unroll
        for (int kk = 0; kk < 64; kk++) wreg[kk] = wrow[kk * 8];
    }
    float c = 0.f, h = 0.f;

    for (int s = 0; s < Ss; s++) {
        const float* gxs = gx + (size_t)s * G4 * Bz;
        float ga0 = gxs[(0 * Hh + j) * Bz + bp * 2 + half];
        float ga1 = gxs[(1 * Hh + j) * Bz + bp * 2 + half];
        float ga2 = gxs[(2 * Hh + j) * Bz + bp * 2 + half];
        float ga3 = gxs[(3 * Hh + j) * Bz + bp * 2 + half];

        if (s > 0) {
            ull acc[16];
            scan_matvec((const float4*)(hbuf + (size_t)(s & 1) * (Hh * Bz)),
                        hsh4, wreg, tid, kc, acc);
            if (lane < 4) {
#pragma unroll
                for (int i = 0; i < 16; i++) gsh[w][g][i] = acc[i];
            }
            __syncwarp();
            const float* gsf = (const float*)&gsh[w][0][0];
            ga0 += gsf[(0 * 16 + bp) * 2 + half];
            ga1 += gsf[(1 * 16 + bp) * 2 + half];
            ga2 += gsf[(2 * 16 + bp) * 2 + half];
            ga3 += gsf[(3 * 16 + bp) * 2 + half];
            __syncwarp();
        }
        lstm_cell(ga0, ga1, ga2, ga3, c, h);
        hbuf[(size_t)((s + 1) & 1) * (Hh * Bz) + (j * 16 + bp) * 2 + half] = h;
        grid_sync(&d_bar_enc, 128);
    }
    d_hfin[(size_t)dir * (Hh * Bz) + (j * 16 + bp) * 2 + half] = h;
    d_cfin[(size_t)dir * (Hh * Bz) + (j * 16 + bp) * 2 + half] = c;
}

// ---- decoder scan: 128 blocks, 4 j/block, 2 warps per j (batch split) ----
__global__ void __launch_bounds__(256) k_dec_scan(const float* __restrict__ Whh) {
    __shared__ float4 hsh4[256 * HS_ROW];
    __shared__ ull gsh[4][2][4][8];   // [j_local][bhalf][gate][pair]
    int tid = threadIdx.x, w = tid >> 5, lane = tid & 31;
    int g = lane & 3, kc = lane >> 2;
    int jl = w >> 1, bhalf = w & 1;
    int j = blockIdx.x * 4 + jl;
    // cell lanes: lane<16 -> pq = lane&7 (pair within half), half = lane>>3
    int pq = lane & 7, chalf = (lane >> 3) & 1;
    int bp = bhalf * 8 + pq;
    bool cell_lane = (lane < 16);

    float wreg[64];
    {
        const float* wrow = Whh + ((size_t)g * Hh + j) * Hh + kc;
#pragma unroll
        for (int kk = 0; kk < 64; kk++) wreg[kk] = wrow[kk * 8];
    }
    float c = cell_lane ? d_c0[(j * 16 + bp) * 2 + chalf] : 0.f;
    float h = 0.f;

    for (int t = 0; t < Tt - 1; t++) {
        const float* gxs = d_gxd + (size_t)t * G4 * Bz;
        float ga0 = 0.f, ga1 = 0.f, ga2 = 0.f, ga3 = 0.f;
        if (cell_lane) {
            ga0 = gxs[(0 * Hh + j) * Bz + bp * 2 + chalf];
            ga1 = gxs[(1 * Hh + j) * Bz + bp * 2 + chalf];
            ga2 = gxs[(2 * Hh + j) * Bz + bp * 2 + chalf];
            ga3 = gxs[(3 * Hh + j) * Bz + bp * 2 + chalf];
        }

        // matvec over this warp's 8 pairs
        ull acc[8];
#pragma unroll
        for (int i = 0; i < 8; i++) acc[i] = 0ULL;
        const float4* src = (const float4*)(d_hdping + (size_t)(t & 1) * (Hh * Bz));
#pragma unroll
        for (int ch = 0; ch < 2; ch++) {
            for (int ii = tid; ii < 2048; ii += 256)
                hsh4[(ii >> 3) * HS_ROW + (ii & 7)] = src[ch * 2048 + ii];
            __syncthreads();
            const ulonglong2* hs2 = (const ulonglong2*)hsh4;
#pragma unroll
            for (int kk2 = 0; kk2 < 32; kk2++) {
                float wv = wreg[ch * 32 + kk2];
                ull w2 = pack2(wv, wv);
                const ulonglong2* row = hs2 + (kc + (kk2 << 3)) * HS_ROW + bhalf * 4;
#pragma unroll
                for (int bq = 0; bq < 4; bq++) {
                    ulonglong2 hv = row[bq];
                    acc[2 * bq]     = ffma2(w2, hv.x, acc[2 * bq]);
                    acc[2 * bq + 1] = ffma2(w2, hv.y, acc[2 * bq + 1]);
                }
            }
            __syncthreads();
        }
#pragma unroll
        for (int i = 0; i < 8; i++) {
            acc[i] = fadd2(acc[i], __shfl_xor_sync(0xffffffffu, acc[i], 4));
            acc[i] = fadd2(acc[i], __shfl_xor_sync(0xffffffffu, acc[i], 8));
            acc[i] = fadd2(acc[i], __shfl_xor_sync(0xffffffffu, acc[i], 16));
        }
        if (lane < 4) {
#pragma unroll
            for (int i = 0; i < 8; i++) gsh[jl][bhalf][g][i] = acc[i];
        }
        __syncwarp();
        if (cell_lane) {
            const float* gsf = (const float*)&gsh[jl][bhalf][0][0];
            ga0 += gsf[(0 * 8 + pq) * 2 + chalf];
            ga1 += gsf[(1 * 8 + pq) * 2 + chalf];
            ga2 += gsf[(2 * 8 + pq) * 2 + chalf];
            ga3 += gsf[(3 * 8 + pq) * 2 + chalf];
            lstm_cell(ga0, ga1, ga2, ga3, c, h);
            d_hdping[(size_t)((t + 1) & 1) * (Hh * Bz) + (j * 16 + bp) * 2 + chalf] = h;
            d_hs[((size_t)t * Bz + bp + 16 * chalf) * Hh + j] = __uint_as_float(cvt_tf32(h));
        }
        grid_sync(&d_bar_dec, 128);
    }
}

__global__ void __launch_bounds__(256) k_h0c0(const float* __restrict__ Wh,
                                              const float* __restrict__ bh,
                                              const float* __restrict__ Wc,
                                              const float* __restrict__ bc) {
    int gg = blockIdx.x * blockDim.x + threadIdx.x;
    int j = gg >> 5, b = gg & 31;
    int bp = b & 15, hf = b >> 4;
    const float* hfp = d_hfin + bp * 2 + hf;
    const float* cfp = d_cfin + bp * 2 + hf;
    const float* whr = Wh + (size_t)j * (2 * Hh);
    const float* wcr = Wc + (size_t)j * (2 * Hh);
    float ah = bh[j], ac = bc[j];
#pragma unroll 8
    for (int k = 0; k < 2 * Hh; k++) {
        ah += whr[k] * hfp[k * 32];
        ac += wcr[k] * cfp[k * 32];
    }
    d_hdping[(j * 16 + bp) * 2 + hf] = ah;
    d_c0[(j * 16 + bp) * 2 + hf] = ac;
}

// =====================================================================
// Logits: register-fragment tf32 mma.sync. CTA 128m x 256n, warp 64x64.
// =====================================================================
#define MMA_TF32(c0, c1, c2, c3, A0, A1, A2, A3, B0, B1) \
    asm volatile( \
        "mma.sync.aligned.m16n8k8.row.col.f32.tf32.tf32.f32 " \
        "{%0,%1,%2,%3},{%4,%5,%6,%7},{%8,%9},{%0,%1,%2,%3};" \
        : "+f"(c0), "+f"(c1), "+f"(c2), "+f"(c3) \
        : "r"(A0), "r"(A1), "r"(A2), "r"(A3), "r"(B0), "r"(B1))

__global__ void __launch_bounds__(256, 1) k_logits_f(const float* __restrict__ fcb,
                                                     float* __restrict__ out) {
    int tid = threadIdx.x, w = tid >> 5, lane = tid & 31;
    int wm = w & 1, wn = w >> 1;
    int mtile = blockIdx.y, ntile = blockIdx.x;

    const float4* Ab = (const float4*)d_atf + (size_t)(mtile * 2 + wm) * 8192 + lane;
    const float4* Bb = (const float4*)d_wtf + (size_t)(ntile * 4 + wn) * 8192 + lane;

    float acc[4][8][4];
#pragma unroll
    for (int a = 0; a < 4; a++)
#pragma unroll
        for (int b = 0; b < 8; b++)
#pragma unroll
            for (int cc = 0; cc < 4; cc++) acc[a][b][cc] = 0.f;

    float4 av[2][4], bv[2][4];
#pragma unroll
    for (int q = 0; q < 4; q++) {
        av[0][q] = Ab[q * 32];
        bv[0][q] = Bb[q * 32];
    }

    for (int ks = 0; ks < 64; ks++) {
        int cur = ks & 1, nxt = cur ^ 1;
        if (ks < 63) {
            const float4* An = Ab + (ks + 1) * 128;
            const float4* Bn = Bb + (ks + 1) * 128;
#pragma unroll
            for (int q = 0; q < 4; q++) {
                av[nxt][q] = An[q * 32];
                bv[nxt][q] = Bn[q * 32];
            }
        }
#pragma unroll
        for (int mt = 0; mt < 4; mt++) {
            unsigned a0 = __float_as_uint(av[cur][mt].x);
            unsigned a1 = __float_as_uint(av[cur][mt].y);
            unsigned a2 = __float_as_uint(av[cur][mt].z);
            unsigned a3 = __float_as_uint(av[cur][mt].w);
#pragma unroll
            for (int p = 0; p < 4; p++) {
                unsigned b0 = __float_as_uint(bv[cur][p].x);
                unsigned b1 = __float_as_uint(bv[cur][p].y);
                unsigned b2 = __float_as_uint(bv[cur][p].z);
                unsigned b3 = __float_as_uint(bv[cur][p].w);
                MMA_TF32(acc[mt][2 * p][0], acc[mt][2 * p][1],
                         acc[mt][2 * p][2], acc[mt][2 * p][3],
                         a0, a1, a2, a3, b0, b1);
                MMA_TF32(acc[mt][2 * p + 1][0], acc[mt][2 * p + 1][1],
                         acc[mt][2 * p + 1][2], acc[mt][2 * p + 1][3],
                         a0, a1, a2, a3, b2, b3);
            }
        }
    }

    int mb = mtile * 128 + wm * 64;
    int nb = ntile * 256 + wn * 64;
#pragma unroll
    for (int mt = 0; mt < 4; mt++) {
        int r0 = mb + mt * 16 + (lane >> 2);
#pragma unroll
        for (int nt = 0; nt < 8; nt++) {
            int n = nb + nt * 8 + (lane & 3) * 2;
            if (n >= Vv) continue;
            float b0 = fcb[n];
            float b1 = fcb[n + 1];
#pragma unroll
            for (int rh = 0; rh < 2; rh++) {
                int m = r0 + rh * 8;
                if (m < 3040) {
                    int b = m & 31, ts = m >> 5;
                    size_t o = ((size_t)b * Tt + ts + 1) * (size_t)Vv + n;
                    out[o]     = acc[mt][nt][rh * 2 + 0] + b0;
                    out[o + 1] = acc[mt][nt][rh * 2 + 1] + b1;
                }
            }
        }
    }
}

extern "C" void kernel_launch(void* const* d_in, const int* in_sizes, int n_in,
                              void* d_out, int out_size) {
    (void)in_sizes; (void)n_in; (void)out_size;
    const int*   Problem   = (const int*)d_in[0];
    const int*   LF        = (const int*)d_in[1];
    const float* enc_embed = (const float*)d_in[2];
    const float* dec_embed = (const float*)d_in[3];
    const float* enc_Wih_f = (const float*)d_in[4];
    const float* enc_Whh_f = (const float*)d_in[5];
    const float* enc_b_f   = (const float*)d_in[6];
    const float* enc_Wih_b = (const float*)d_in[7];
    const float* enc_Whh_b = (const float*)d_in[8];
    const float* enc_b_b   = (const float*)d_in[9];
    const float* Wh        = (const float*)d_in[10];
    const float* bh        = (const float*)d_in[11];
    const float* Wc        = (const float*)d_in[12];
    const float* bc        = (const float*)d_in[13];
    const float* dec_Wih   = (const float*)d_in[14];
    const float* dec_Whh   = (const float*)d_in[15];
    const float* dec_b     = (const float*)d_in[16];
    const float* fc_W      = (const float*)d_in[17];
    const float* fc_b      = (const float*)d_in[18];
    float* out = (float*)d_out;

    // launch order chosen so ncu (-s 5) captures k_enc_scan next round
    k_idx<<<12, 256>>>(Problem, LF);                       // 0
    k_zero_t0<<<(Bz * Vv + 255) / 256, 256>>>(out);        // 1
    {
        dim3 g(G4 / 64, (Ss * Bz) / 64);
        k_sgemm<<<g, 256>>>(enc_embed, enc_Wih_f, enc_b_f, Ss * Bz, G4, Ee, 0, 0); // 2
        k_sgemm<<<g, 256>>>(enc_embed, enc_Wih_b, enc_b_b, Ss * Bz, G4, Ee, 1, 1); // 3
    }
    {
        dim3 g(G4 / 64, ((Tt - 1) * Bz + 63) / 64);
        k_sgemm<<<g, 256>>>(dec_embed, dec_Wih, dec_b, (Tt - 1) * Bz, G4, Ee, 2, 2); // 4
    }

    k_enc_scan<<<128, 256>>>(enc_Whh_f, enc_Whh_b);        // 5  <- profiled
    k_h0c0<<<64, 256>>>(Wh, bh, Wc, bc);                   // 6
    k_dec_scan<<<128, 256>>>(dec_Whh);                     // 7
    k_permW<<<VPAD * Hh / 4 / 256, 256>>>(fc_W);           // 8
    k_permA<<<MPAD * Hh / 4 / 256, 256>>>();               // 9

    {
        dim3 g(VPAD / 256, MPAD / 128);   // 118 x 24
        k_logits_f<<<g, 256>>>(fc_b, out);                 // 10
    }
}

// round 9
// speedup vs baseline: 3.6573x; 1.0315x over previous
#include <cuda_runtime.h>
#include <math.h>
#include <stdint.h>

#define Bz 32
#define Ss 96
#define Tt 96
#define Ee 200
#define Hh 512
#define Vv 30000
#define G4 2048
#define VPAD 30208   // 118 * 256
#define MPAD 3072    // 24 * 128
#define XM 3072
#define XN 2048
#define XK 200

typedef unsigned long long ull;

// Pair layout for (k,b) arrays: element (k,b) at [(k*16+(b&15))*2 + (b>>4)]
__device__ float d_gxf[(size_t)Ss * G4 * Bz];
__device__ float d_gxb[(size_t)Ss * G4 * Bz];
__device__ float d_gxd[(size_t)(Tt - 1) * G4 * Bz];
__device__ float d_hping[2 * 2 * Hh * Bz];
__device__ float d_hdping[2 * Hh * Bz];
__device__ float d_hfin[2 * Hh * Bz];
__device__ float d_cfin[2 * Hh * Bz];
__device__ float d_c0[Hh * Bz];
__device__ float d_wtf[(size_t)VPAD * Hh];     // fc_W fragment-permuted (tf32)
__device__ float d_atf[(size_t)MPAD * Hh];     // decoder h fragment-permuted (tf32)
// x-gemm operand buffers (hi/lo tf32 split, fragment order)
__device__ float d_xah[3][XM * XK];
__device__ float d_xal[3][XM * XK];
__device__ float d_xbh[3][XN * XK];
__device__ float d_xbl[3][XN * XK];
__device__ int d_idxf[Ss * Bz];
__device__ int d_idxb[Ss * Bz];
__device__ int d_idxd[(Tt - 1) * Bz];
// hierarchical barrier counters (leaf entries 128B apart)
__device__ ull d_lf_enc[8 * 16];
__device__ ull d_rt_enc;
__device__ ull d_lf_dec[8 * 16];
__device__ ull d_rt_dec;

__device__ __forceinline__ ull pack2(float x, float y) {
    ull r; asm("mov.b64 %0,{%1,%2};" : "=l"(r) : "f"(x), "f"(y)); return r;
}
__device__ __forceinline__ ull ffma2(ull a, ull b, ull c) {
    ull d; asm("fma.rn.f32x2 %0,%1,%2,%3;" : "=l"(d) : "l"(a), "l"(b), "l"(c)); return d;
}
__device__ __forceinline__ ull fadd2(ull a, ull b) {
    ull d; asm("add.rn.f32x2 %0,%1,%2;" : "=l"(d) : "l"(a), "l"(b)); return d;
}
__device__ __forceinline__ unsigned cvt_tf32(float x) {
    unsigned u; asm("cvt.rna.tf32.f32 %0,%1;" : "=r"(u) : "f"(x)); return u;
}
__device__ __forceinline__ float tf32f(float x) { return __uint_as_float(cvt_tf32(x)); }

// 2-level grid barrier: 16 blocks/leaf, 8 leaves. Monotone counters
// (graph-replay safe); phase derived from this block's own leaf ticket.
__device__ __forceinline__ void grid_sync2(ull* leaf, ull* root, int bid) {
    __syncthreads();
    if (threadIdx.x == 0) {
        __threadfence();
        ull a = atomicAdd(&leaf[(bid >> 4) * 16], 1ULL) + 1ULL;
        ull phase = (a - 1ULL) >> 4;           // 16 arrivals per leaf per phase
        if ((a & 15ULL) == 0ULL) atomicAdd(root, 1ULL);
        ull target = (phase + 1ULL) * 8ULL;    // 8 leaves per phase
        while (*((volatile ull*)root) < target) { }
        __threadfence();
    }
    __syncthreads();
}

__global__ void k_idx(const int* __restrict__ Problem, const int* __restrict__ LF) {
    int m = blockIdx.x * blockDim.x + threadIdx.x;
    if (m < Ss * Bz) {
        int s = m >> 5, b = m & 31;
        d_idxf[m] = Problem[b * Ss + s];
        d_idxb[m] = Problem[b * Ss + (Ss - 1 - s)];
    }
    if (m < (Tt - 1) * Bz) {
        int t = m >> 5, b = m & 31;
        d_idxd[m] = LF[b * Tt + t];
    }
}

__global__ void k_zero_t0(float* __restrict__ out) {
    long i = (long)blockIdx.x * blockDim.x + threadIdx.x;
    if (i < (long)Bz * Vv) {
        long b = i / Vv;
        long n = i - b * Vv;
        out[b * (long)Tt * Vv + n] = 0.f;
    }
}

// zero the padded warp-tile (rows 3008..3071) of d_atf; dec scan overwrites
// rows 3008..3039, leaving the 3040..3071 pad zero.
__global__ void k_zero_pad() {
    float4* p = (float4*)d_atf + (size_t)47 * 8192;
    for (int i = threadIdx.x + blockIdx.x * 256; i < 8192; i += 512)
        p[i] = make_float4(0.f, 0.f, 0.f, 0.f);
}

// ---- fc_W -> tf32, fragment-permuted, padded to VPAD --------------------
__global__ void __launch_bounds__(256) k_permW(const float* __restrict__ W) {
    int o = blockIdx.x * 256 + threadIdx.x;
    int lane = o & 31;
    int p = (o >> 5) & 3;
    int ks = (o >> 7) & 63;
    int wn = (o >> 13) & 3;
    int ntile = o >> 15;
    int n0 = ntile * 256 + wn * 64 + p * 16 + (lane >> 2);
    int kl = ks * 8 + (lane & 3);
    float4 v = make_float4(0.f, 0.f, 0.f, 0.f);
    if (n0 < Vv) {
        v.x = W[(size_t)n0 * Hh + kl];
        v.y = W[(size_t)n0 * Hh + kl + 4];
    }
    if (n0 + 8 < Vv) {
        v.z = W[(size_t)(n0 + 8) * Hh + kl];
        v.w = W[(size_t)(n0 + 8) * Hh + kl + 4];
    }
    v.x = tf32f(v.x); v.y = tf32f(v.y); v.z = tf32f(v.z); v.w = tf32f(v.w);
    ((float4*)d_wtf)[o] = v;
}

// ---- gathered embeddings -> hi/lo tf32 fragments (A of x-gemm) ----------
__global__ void __launch_bounds__(256) k_permX(const float* __restrict__ E,
                                               int which, int Mlim) {
    int o = blockIdx.x * 256 + threadIdx.x;   // < 153600
    const int* ridx = (which == 0) ? d_idxf : (which == 1) ? d_idxb : d_idxd;
    int lane = o & 31, q = (o >> 5) & 3;
    int t7 = o >> 7;
    int ks = t7 % 25, wt = t7 / 25;
    int m0 = wt * 64 + q * 16 + (lane >> 2);
    int kl = ks * 8 + (lane & 3);
    float a0 = 0.f, a1 = 0.f, a2 = 0.f, a3 = 0.f;
    if (m0 < Mlim) {
        const float* r = E + (size_t)ridx[m0] * XK;
        a0 = r[kl]; a2 = r[kl + 4];
    }
    if (m0 + 8 < Mlim) {
        const float* r = E + (size_t)ridx[m0 + 8] * XK;
        a1 = r[kl]; a3 = r[kl + 4];
    }
    float4 hi, lo;
    hi.x = tf32f(a0); lo.x = tf32f(a0 - hi.x);
    hi.y = tf32f(a1); lo.y = tf32f(a1 - hi.y);
    hi.z = tf32f(a2); lo.z = tf32f(a2 - hi.z);
    hi.w = tf32f(a3); lo.w = tf32f(a3 - hi.w);
    ((float4*)d_xah[which])[o] = hi;
    ((float4*)d_xal[which])[o] = lo;
}

// ---- Wih -> hi/lo tf32 fragments (B of x-gemm) --------------------------
__global__ void __launch_bounds__(256) k_permWih(const float* __restrict__ W,
                                                 int which) {
    int o = blockIdx.x * 256 + threadIdx.x;   // < 102400
    int lane = o & 31, p = (o >> 5) & 1;
    int t6 = o >> 6;
    int ks = t6 % 25, wt = t6 / 25;
    int n0 = wt * 32 + p * 16 + (lane >> 2);
    int kl = ks * 8 + (lane & 3);
    float b0 = W[(size_t)n0 * XK + kl];
    float b1 = W[(size_t)n0 * XK + kl + 4];
    float b2 = W[(size_t)(n0 + 8) * XK + kl];
    float b3 = W[(size_t)(n0 + 8) * XK + kl + 4];
    float4 hi, lo;
    hi.x = tf32f(b0); lo.x = tf32f(b0 - hi.x);
    hi.y = tf32f(b1); lo.y = tf32f(b1 - hi.y);
    hi.z = tf32f(b2); lo.z = tf32f(b2 - hi.z);
    hi.w = tf32f(b3); lo.w = tf32f(b3 - hi.w);
    ((float4*)d_xbh[which])[o] = hi;
    ((float4*)d_xbl[which])[o] = lo;
}

#define MMA_TF32(c0, c1, c2, c3, A0, A1, A2, A3, B0, B1) \
    asm volatile( \
        "mma.sync.aligned.m16n8k8.row.col.f32.tf32.tf32.f32 " \
        "{%0,%1,%2,%3},{%4,%5,%6,%7},{%8,%9},{%0,%1,%2,%3};" \
        : "+f"(c0), "+f"(c1), "+f"(c2), "+f"(c3) \
        : "r"(A0), "r"(A1), "r"(A2), "r"(A3), "r"(B0), "r"(B1))

// ---- x-gate GEMM, 3xTF32 (near-fp32): gates = Ah·Bh + Ah·Bl + Al·Bh -----
// CTA 128m x 128n, 8 warps (2wm x 4wn), warp 64x32. Pair-layout output.
__global__ void __launch_bounds__(256) k_xg(const float* __restrict__ bias,
                                            int which, int Mlim) {
    float* out = (which == 0) ? d_gxf : (which == 1) ? d_gxb : d_gxd;
    int tid = threadIdx.x, w = tid >> 5, lane = tid & 31;
    int wm = w & 1, wn = w >> 1;
    const float4* Ah = (const float4*)d_xah[which] + (size_t)(blockIdx.y * 2 + wm) * 3200 + lane;
    const float4* Al = (const float4*)d_xal[which] + (size_t)(blockIdx.y * 2 + wm) * 3200 + lane;
    const float4* Bh = (const float4*)d_xbh[which] + (size_t)(blockIdx.x * 4 + wn) * 1600 + lane;
    const float4* Bl = (const float4*)d_xbl[which] + (size_t)(blockIdx.x * 4 + wn) * 1600 + lane;

    float acc[4][4][4];
#pragma unroll
    for (int a = 0; a < 4; a++)
#pragma unroll
        for (int b = 0; b < 4; b++)
#pragma unroll
            for (int cc = 0; cc < 4; cc++) acc[a][b][cc] = 0.f;

    for (int ks = 0; ks < 25; ks++) {
        float4 ah[4], al[4], bh[2], bl[2];
#pragma unroll
        for (int q = 0; q < 4; q++) {
            ah[q] = Ah[ks * 128 + q * 32];
            al[q] = Al[ks * 128 + q * 32];
        }
#pragma unroll
        for (int p = 0; p < 2; p++) {
            bh[p] = Bh[ks * 64 + p * 32];
            bl[p] = Bl[ks * 64 + p * 32];
        }
#pragma unroll
        for (int mt = 0; mt < 4; mt++) {
            unsigned h0 = __float_as_uint(ah[mt].x), h1 = __float_as_uint(ah[mt].y);
            unsigned h2 = __float_as_uint(ah[mt].z), h3 = __float_as_uint(ah[mt].w);
            unsigned l0 = __float_as_uint(al[mt].x), l1 = __float_as_uint(al[mt].y);
            unsigned l2 = __float_as_uint(al[mt].z), l3 = __float_as_uint(al[mt].w);
#pragma unroll
            for (int n8 = 0; n8 < 4; n8++) {
                int p = n8 >> 1;
                unsigned wh0, wh1, wl0, wl1;
                if (n8 & 1) { wh0 = __float_as_uint(bh[p].z); wh1 = __float_as_uint(bh[p].w);
                              wl0 = __float_as_uint(bl[p].z); wl1 = __float_as_uint(bl[p].w); }
                else        { wh0 = __float_as_uint(bh[p].x); wh1 = __float_as_uint(bh[p].y);
                              wl0 = __float_as_uint(bl[p].x); wl1 = __float_as_uint(bl[p].y); }
                MMA_TF32(acc[mt][n8][0], acc[mt][n8][1], acc[mt][n8][2], acc[mt][n8][3],
                         h0, h1, h2, h3, wh0, wh1);
                MMA_TF32(acc[mt][n8][0], acc[mt][n8][1], acc[mt][n8][2], acc[mt][n8][3],
                         h0, h1, h2, h3, wl0, wl1);
                MMA_TF32(acc[mt][n8][0], acc[mt][n8][1], acc[mt][n8][2], acc[mt][n8][3],
                         l0, l1, l2, l3, wh0, wh1);
            }
        }
    }

    int mb = blockIdx.y * 128 + wm * 64;
    int nb = blockIdx.x * 128 + wn * 32;
#pragma unroll
    for (int mt = 0; mt < 4; mt++) {
        int r0 = mb + mt * 16 + (lane >> 2);
#pragma unroll
        for (int n8 = 0; n8 < 4; n8++) {
            int n = nb + n8 * 8 + (lane & 3) * 2;
            float b0 = bias[n], b1 = bias[n + 1];
#pragma unroll
            for (int rh = 0; rh < 2; rh++) {
                int m = r0 + rh * 8;
                if (m < Mlim) {
                    size_t base = ((size_t)(m >> 5) * XN + n) * 32 + (m & 15) * 2 + ((m >> 4) & 1);
                    out[base]      = acc[mt][n8][rh * 2 + 0] + b0;
                    out[base + 32] = acc[mt][n8][rh * 2 + 1] + b1;
                }
            }
        }
    }
}

__device__ __forceinline__ void lstm_cell(float ai, float af, float ag, float ao,
                                          float& c, float& h) {
    float si = 1.f / (1.f + expf(-ai));
    float sf = 1.f / (1.f + expf(-af));
    float so = 1.f / (1.f + expf(-ao));
    float tg = tanhf(ag);
    c = sf * c + si * tg;
    h = so * tanhf(c);
}

#define HS_ROW 9

// full-batch matvec (encoder: 1 warp per j, 16 pairs)
__device__ __forceinline__ void scan_matvec(
    const float4* __restrict__ src, float4* hsh4, float wreg[64],
    int tid, int kc, ull acc[16])
{
#pragma unroll
    for (int i = 0; i < 16; i++) acc[i] = 0ULL;
#pragma unroll
    for (int ch = 0; ch < 2; ch++) {
        for (int ii = tid; ii < 2048; ii += 256)
            hsh4[(ii >> 3) * HS_ROW + (ii & 7)] = src[ch * 2048 + ii];
        __syncthreads();
        const ulonglong2* hs2 = (const ulonglong2*)hsh4;
#pragma unroll
        for (int kk2 = 0; kk2 < 32; kk2++) {
            float wv = wreg[ch * 32 + kk2];
            ull w2 = pack2(wv, wv);
            const ulonglong2* row = hs2 + (kc + (kk2 << 3)) * HS_ROW;
#pragma unroll
            for (int bq = 0; bq < 8; bq++) {
                ulonglong2 hv = row[bq];
                acc[2 * bq]     = ffma2(w2, hv.x, acc[2 * bq]);
                acc[2 * bq + 1] = ffma2(w2, hv.y, acc[2 * bq + 1]);
            }
        }
        __syncthreads();
    }
#pragma unroll
    for (int i = 0; i < 16; i++) {
        acc[i] = fadd2(acc[i], __shfl_xor_sync(0xffffffffu, acc[i], 4));
        acc[i] = fadd2(acc[i], __shfl_xor_sync(0xffffffffu, acc[i], 8));
        acc[i] = fadd2(acc[i], __shfl_xor_sync(0xffffffffu, acc[i], 16));
    }
}

__global__ void __launch_bounds__(256) k_enc_scan(const float* __restrict__ Whf,
                                                  const float* __restrict__ Whb) {
    __shared__ float4 hsh4[256 * HS_ROW];
    __shared__ ull gsh[8][4][16];
    int tid = threadIdx.x, w = tid >> 5, lane = tid & 31;
    int g = lane & 3, kc = lane >> 2;
    int bp = lane & 15, half = lane >> 4;
    int dir = blockIdx.x >> 6;
    int j = (blockIdx.x & 63) * 8 + w;

    const float* gx = dir ? d_gxb : d_gxf;
    const float* Whh = dir ? Whb : Whf;
    float* hbuf = d_hping + (size_t)dir * (2 * Hh * Bz);

    float wreg[64];
    {
        const float* wrow = Whh + ((size_t)g * Hh + j) * Hh + kc;
#pragma unroll
        for (int kk = 0; kk < 64; kk++) wreg[kk] = wrow[kk * 8];
    }
    float c = 0.f, h = 0.f;

    for (int s = 0; s < Ss; s++) {
        const float* gxs = gx + (size_t)s * G4 * Bz;
        float ga0 = gxs[(0 * Hh + j) * Bz + bp * 2 + half];
        float ga1 = gxs[(1 * Hh + j) * Bz + bp * 2 + half];
        float ga2 = gxs[(2 * Hh + j) * Bz + bp * 2 + half];
        float ga3 = gxs[(3 * Hh + j) * Bz + bp * 2 + half];

        if (s > 0) {
            ull acc[16];
            scan_matvec((const float4*)(hbuf + (size_t)(s & 1) * (Hh * Bz)),
                        hsh4, wreg, tid, kc, acc);
            if (lane < 4) {
#pragma unroll
                for (int i = 0; i < 16; i++) gsh[w][g][i] = acc[i];
            }
            __syncwarp();
            const float* gsf = (const float*)&gsh[w][0][0];
            ga0 += gsf[(0 * 16 + bp) * 2 + half];
            ga1 += gsf[(1 * 16 + bp) * 2 + half];
            ga2 += gsf[(2 * 16 + bp) * 2 + half];
            ga3 += gsf[(3 * 16 + bp) * 2 + half];
            __syncwarp();
        }
        lstm_cell(ga0, ga1, ga2, ga3, c, h);
        hbuf[(size_t)((s + 1) & 1) * (Hh * Bz) + (j * 16 + bp) * 2 + half] = h;
        grid_sync2(d_lf_enc, &d_rt_enc, blockIdx.x);
    }
    d_hfin[(size_t)dir * (Hh * Bz) + (j * 16 + bp) * 2 + half] = h;
    d_cfin[(size_t)dir * (Hh * Bz) + (j * 16 + bp) * 2 + half] = c;
}

// ---- decoder scan: 128 blocks, 4 j/block, 2 warps per j (batch split) ----
// writes h directly in logits fragment layout (d_atf)
__global__ void __launch_bounds__(256) k_dec_scan(const float* __restrict__ Whh) {
    __shared__ float4 hsh4[256 * HS_ROW];
    __shared__ ull gsh[4][2][4][8];
    int tid = threadIdx.x, w = tid >> 5, lane = tid & 31;
    int g = lane & 3, kc = lane >> 2;
    int jl = w >> 1, bhalf = w & 1;
    int j = blockIdx.x * 4 + jl;
    int pq = lane & 7, chalf = (lane >> 3) & 1;
    int bp = bhalf * 8 + pq;
    bool cell_lane = (lane < 16);

    float wreg[64];
    {
        const float* wrow = Whh + ((size_t)g * Hh + j) * Hh + kc;
#pragma unroll
        for (int kk = 0; kk < 64; kk++) wreg[kk] = wrow[kk * 8];
    }
    float c = cell_lane ? d_c0[(j * 16 + bp) * 2 + chalf] : 0.f;
    float h = 0.f;

    for (int t = 0; t < Tt - 1; t++) {
        const float* gxs = d_gxd + (size_t)t * G4 * Bz;
        float ga0 = 0.f, ga1 = 0.f, ga2 = 0.f, ga3 = 0.f;
        if (cell_lane) {
            ga0 = gxs[(0 * Hh + j) * Bz + bp * 2 + chalf];
            ga1 = gxs[(1 * Hh + j) * Bz + bp * 2 + chalf];
            ga2 = gxs[(2 * Hh + j) * Bz + bp * 2 + chalf];
            ga3 = gxs[(3 * Hh + j) * Bz + bp * 2 + chalf];
        }

        ull acc[8];
#pragma unroll
        for (int i = 0; i < 8; i++) acc[i] = 0ULL;
        const float4* src = (const float4*)(d_hdping + (size_t)(t & 1) * (Hh * Bz));
#pragma unroll
        for (int ch = 0; ch < 2; ch++) {
            for (int ii = tid; ii < 2048; ii += 256)
                hsh4[(ii >> 3) * HS_ROW + (ii & 7)] = src[ch * 2048 + ii];
            __syncthreads();
            const ulonglong2* hs2 = (const ulonglong2*)hsh4;
#pragma unroll
            for (int kk2 = 0; kk2 < 32; kk2++) {
                float wv = wreg[ch * 32 + kk2];
                ull w2 = pack2(wv, wv);
                const ulonglong2* row = hs2 + (kc + (kk2 << 3)) * HS_ROW + bhalf * 4;
#pragma unroll
                for (int bq = 0; bq < 4; bq++) {
                    ulonglong2 hv = row[bq];
                    acc[2 * bq]     = ffma2(w2, hv.x, acc[2 * bq]);
                    acc[2 * bq + 1] = ffma2(w2, hv.y, acc[2 * bq + 1]);
                }
            }
            __syncthreads();
        }
#pragma unroll
        for (int i = 0; i < 8; i++) {
            acc[i] = fadd2(acc[i], __shfl_xor_sync(0xffffffffu, acc[i], 4));
            acc[i] = fadd2(acc[i], __shfl_xor_sync(0xffffffffu, acc[i], 8));
            acc[i] = fadd2(acc[i], __shfl_xor_sync(0xffffffffu, acc[i], 16));
        }
        if (lane < 4) {
#pragma unroll
            for (int i = 0; i < 8; i++) gsh[jl][bhalf][g][i] = acc[i];
        }
        __syncwarp();
        if (cell_lane) {
            const float* gsf = (const float*)&gsh[jl][bhalf][0][0];
            ga0 += gsf[(0 * 8 + pq) * 2 + chalf];
            ga1 += gsf[(1 * 8 + pq) * 2 + chalf];
            ga2 += gsf[(2 * 8 + pq) * 2 + chalf];
            ga3 += gsf[(3 * 8 + pq) * 2 + chalf];
            lstm_cell(ga0, ga1, ga2, ga3, c, h);
            d_hdping[(size_t)((t + 1) & 1) * (Hh * Bz) + (j * 16 + bp) * 2 + chalf] = h;
            // fragment-layout store (replaces d_hs + k_permA)
            int mrow = t * 32 + bp + 16 * chalf;
            size_t f4 = (size_t)(mrow >> 6) * 8192 + (j >> 3) * 128
                      + ((mrow >> 4) & 3) * 32 + (mrow & 7) * 4 + (j & 3);
            int comp = ((mrow >> 3) & 1) + 2 * ((j >> 2) & 1);
            d_atf[4 * f4 + comp] = tf32f(h);
        }
        grid_sync2(d_lf_dec, &d_rt_dec, blockIdx.x);
    }
}

__global__ void __launch_bounds__(256) k_h0c0(const float* __restrict__ Wh,
                                              const float* __restrict__ bh,
                                              const float* __restrict__ Wc,
                                              const float* __restrict__ bc) {
    int gg = blockIdx.x * blockDim.x + threadIdx.x;
    int j = gg >> 5, b = gg & 31;
    int bp = b & 15, hf = b >> 4;
    const float* hfp = d_hfin + bp * 2 + hf;
    const float* cfp = d_cfin + bp * 2 + hf;
    const float* whr = Wh + (size_t)j * (2 * Hh);
    const float* wcr = Wc + (size_t)j * (2 * Hh);
    float ah = bh[j], ac = bc[j];
#pragma unroll 8
    for (int k = 0; k < 2 * Hh; k++) {
        ah += whr[k] * hfp[k * 32];
        ac += wcr[k] * cfp[k * 32];
    }
    d_hdping[(j * 16 + bp) * 2 + hf] = ah;
    d_c0[(j * 16 + bp) * 2 + hf] = ac;
}

// Logits: register-fragment tf32 mma.sync. CTA 128m x 256n, warp 64x64.
__global__ void __launch_bounds__(256, 1) k_logits_f(const float* __restrict__ fcb,
                                                     float* __restrict__ out) {
    int tid = threadIdx.x, w = tid >> 5, lane = tid & 31;
    int wm = w & 1, wn = w >> 1;
    int mtile = blockIdx.y, ntile = blockIdx.x;

    const float4* Ab = (const float4*)d_atf + (size_t)(mtile * 2 + wm) * 8192 + lane;
    const float4* Bb = (const float4*)d_wtf + (size_t)(ntile * 4 + wn) * 8192 + lane;

    float acc[4][8][4];
#pragma unroll
    for (int a = 0; a < 4; a++)
#pragma unroll
        for (int b = 0; b < 8; b++)
#pragma unroll
            for (int cc = 0; cc < 4; cc++) acc[a][b][cc] = 0.f;

    float4 av[2][4], bv[2][4];
#pragma unroll
    for (int q = 0; q < 4; q++) {
        av[0][q] = Ab[q * 32];
        bv[0][q] = Bb[q * 32];
    }

    for (int ks = 0; ks < 64; ks++) {
        int cur = ks & 1, nxt = cur ^ 1;
        if (ks < 63) {
            const float4* An = Ab + (ks + 1) * 128;
            const float4* Bn = Bb + (ks + 1) * 128;
#pragma unroll
            for (int q = 0; q < 4; q++) {
                av[nxt][q] = An[q * 32];
                bv[nxt][q] = Bn[q * 32];
            }
        }
#pragma unroll
        for (int mt = 0; mt < 4; mt++) {
            unsigned a0 = __float_as_uint(av[cur][mt].x);
            unsigned a1 = __float_as_uint(av[cur][mt].y);
            unsigned a2 = __float_as_uint(av[cur][mt].z);
            unsigned a3 = __float_as_uint(av[cur][mt].w);
#pragma unroll
            for (int p = 0; p < 4; p++) {
                unsigned b0 = __float_as_uint(bv[cur][p].x);
                unsigned b1 = __float_as_uint(bv[cur][p].y);
                unsigned b2 = __float_as_uint(bv[cur][p].z);
                unsigned b3 = __float_as_uint(bv[cur][p].w);
                MMA_TF32(acc[mt][2 * p][0], acc[mt][2 * p][1],
                         acc[mt][2 * p][2], acc[mt][2 * p][3],
                         a0, a1, a2, a3, b0, b1);
                MMA_TF32(acc[mt][2 * p + 1][0], acc[mt][2 * p + 1][1],
                         acc[mt][2 * p + 1][2], acc[mt][2 * p + 1][3],
                         a0, a1, a2, a3, b2, b3);
            }
        }
    }

    int mb = mtile * 128 + wm * 64;
    int nb = ntile * 256 + wn * 64;
#pragma unroll
    for (int mt = 0; mt < 4; mt++) {
        int r0 = mb + mt * 16 + (lane >> 2);
#pragma unroll
        for (int nt = 0; nt < 8; nt++) {
            int n = nb + nt * 8 + (lane & 3) * 2;
            if (n >= Vv) continue;
            float b0 = fcb[n];
            float b1 = fcb[n + 1];
#pragma unroll
            for (int rh = 0; rh < 2; rh++) {
                int m = r0 + rh * 8;
                if (m < 3040) {
                    int b = m & 31, ts = m >> 5;
                    size_t o = ((size_t)b * Tt + ts + 1) * (size_t)Vv + n;
                    out[o]     = acc[mt][nt][rh * 2 + 0] + b0;
                    out[o + 1] = acc[mt][nt][rh * 2 + 1] + b1;
                }
            }
        }
    }
}

extern "C" void kernel_launch(void* const* d_in, const int* in_sizes, int n_in,
                              void* d_out, int out_size) {
    (void)in_sizes; (void)n_in; (void)out_size;
    const int*   Problem   = (const int*)d_in[0];
    const int*   LF        = (const int*)d_in[1];
    const float* enc_embed = (const float*)d_in[2];
    const float* dec_embed = (const float*)d_in[3];
    const float* enc_Wih_f = (const float*)d_in[4];
    const float* enc_Whh_f = (const float*)d_in[5];
    const float* enc_b_f   = (const float*)d_in[6];
    const float* enc_Wih_b = (const float*)d_in[7];
    const float* enc_Whh_b = (const float*)d_in[8];
    const float* enc_b_b   = (const float*)d_in[9];
    const float* Wh        = (const float*)d_in[10];
    const float* bh        = (const float*)d_in[11];
    const float* Wc        = (const float*)d_in[12];
    const float* bc        = (const float*)d_in[13];
    const float* dec_Wih   = (const float*)d_in[14];
    const float* dec_Whh   = (const float*)d_in[15];
    const float* dec_b     = (const float*)d_in[16];
    const float* fc_W      = (const float*)d_in[17];
    const float* fc_b      = (const float*)d_in[18];
    float* out = (float*)d_out;

    k_idx<<<12, 256>>>(Problem, LF);
    k_zero_t0<<<(Bz * Vv + 255) / 256, 256>>>(out);
    k_zero_pad<<<2, 256>>>();

    // x-gate operand perms (hi/lo tf32 fragments)
    k_permX<<<600, 256>>>(enc_embed, 0, XM);
    k_permX<<<600, 256>>>(enc_embed, 1, XM);
    k_permX<<<600, 256>>>(dec_embed, 2, 3040);
    k_permWih<<<400, 256>>>(enc_Wih_f, 0);
    k_permWih<<<400, 256>>>(enc_Wih_b, 1);
    k_permWih<<<400, 256>>>(dec_Wih, 2);

    // x-gate GEMMs (3xTF32 tensor path)
    {
        dim3 g(XN / 128, XM / 128);   // 16 x 24
        k_xg<<<g, 256>>>(enc_b_f, 0, XM);
        k_xg<<<g, 256>>>(enc_b_b, 1, XM);
        k_xg<<<g, 256>>>(dec_b, 2, 3040);
    }

    k_enc_scan<<<128, 256>>>(enc_Whh_f, enc_Whh_b);
    k_h0c0<<<64, 256>>>(Wh, bh, Wc, bc);
    k_dec_scan<<<128, 256>>>(dec_Whh);
    k_permW<<<VPAD * Hh / 4 / 256, 256>>>(fc_W);

    {
        dim3 g(VPAD / 256, MPAD / 128);   // 118 x 24
        k_logits_f<<<g, 256>>>(fc_b, out);
    }
}